// round 10
// baseline (speedup 1.0000x reference)
#include <cuda_runtime.h>
#include <math.h>
#include <stdint.h>

typedef unsigned long long ull;

#define CB 4
#define CS 2048
#define CD 1024
#define CH 16
#define NROWS (CB*CS)          // 8192
#define QKV_LD 3072

// ---------------- scratch (static device globals: allocation-free) ----------
__device__ float g_qnorm[(size_t)NROWS*CD];      // 32 MB
__device__ float g_qkv[(size_t)NROWS*QKV_LD];    // 96 MB : [Q(1024)|K(1024)|V(1024)]
__device__ float g_ctx[(size_t)NROWS*CD];        // 32 MB

// ---------------- f32x2 helpers (FFMA2: full-rate fp32 on sm_10x) -----------
__device__ __forceinline__ ull pack2(float x, float y){
    ull r; asm("mov.b64 %0, {%1,%2};" : "=l"(r) : "f"(x), "f"(y)); return r;
}
__device__ __forceinline__ ull fma2(ull a, ull b, ull c){
    ull d; asm("fma.rn.f32x2 %0, %1, %2, %3;" : "=l"(d) : "l"(a), "l"(b), "l"(c)); return d;
}
__device__ __forceinline__ ull mul2(ull a, ull b){
    ull d; asm("mul.rn.f32x2 %0, %1, %2;" : "=l"(d) : "l"(a), "l"(b)); return d;
}
__device__ __forceinline__ float2 unpack2(ull v){
    float2 f; asm("mov.b64 {%0,%1}, %2;" : "=f"(f.x), "=f"(f.y) : "l"(v)); return f;
}
__device__ __forceinline__ float ex2(float x){
    float r; asm("ex2.approx.ftz.f32 %0, %1;" : "=f"(r) : "f"(x)); return r;
}
#define NEG_INF (__int_as_float(0xff800000))

// ---------------- LayerNorm: one block per row (round-1 exact) ---------------
__global__ __launch_bounds__(256) void ln_kernel(
    const float* __restrict__ x, const float* __restrict__ gamma,
    const float* __restrict__ beta)
{
    __shared__ float rs[8], rss[8];
    __shared__ float mu_s, rstd_s;
    int row = blockIdx.x, t = threadIdx.x;
    float4 v = ((const float4*)(x + (size_t)row*CD))[t];
    float s  = v.x+v.y+v.z+v.w;
    float ss = v.x*v.x+v.y*v.y+v.z*v.z+v.w*v.w;
    #pragma unroll
    for (int o=16;o>0;o>>=1){ s += __shfl_xor_sync(~0u,s,o); ss += __shfl_xor_sync(~0u,ss,o); }
    if ((t&31)==0){ rs[t>>5]=s; rss[t>>5]=ss; }
    __syncthreads();
    if (t<32){
        float a  = t<8 ? rs[t]  : 0.f;
        float bq = t<8 ? rss[t] : 0.f;
        #pragma unroll
        for (int o=4;o>0;o>>=1){ a += __shfl_xor_sync(~0u,a,o); bq += __shfl_xor_sync(~0u,bq,o); }
        if (t==0){
            float mu  = a*(1.f/CD);
            float var = bq*(1.f/CD) - mu*mu;
            mu_s = mu; rstd_s = rsqrtf(var + 1e-3f);
        }
    }
    __syncthreads();
    float mu = mu_s, r = rstd_s;
    float4 g = ((const float4*)gamma)[t], bb = ((const float4*)beta)[t];
    float4 o;
    o.x=(v.x-mu)*r*g.x+bb.x; o.y=(v.y-mu)*r*g.y+bb.y;
    o.z=(v.z-mu)*r*g.z+bb.z; o.w=(v.w-mu)*r*g.w+bb.w;
    ((float4*)(g_qnorm + (size_t)row*CD))[t] = o;
}

// ---------------- 128x128x16 SGEMM, double-buffered smem ---------------------
// mode 0: C=g_qkv(+0)   A=g_qnorm  (Q proj)
// mode 1: C=g_qkv+1024  A=g_qnorm  (KV proj)
// mode 2: C=outp        A=g_ctx, resid=g_qnorm (O proj)
__global__ __launch_bounds__(256) void gemm_kernel(
    int mode, const float* __restrict__ W, const float* __restrict__ bias,
    float* __restrict__ outp, int ldw, int ldc)
{
    __shared__ float As[2][16][132];
    __shared__ float Bs[2][16][128];
    const int K = CD;
    const float* A; float* C; const float* resid = nullptr;
    if (mode==0)      { A = g_qnorm; C = g_qkv; }
    else if (mode==1) { A = g_qnorm; C = g_qkv + 1024; }
    else              { A = g_ctx;   C = outp;  resid = g_qnorm; }

    int m0 = blockIdx.x*128, n0 = blockIdx.y*128;
    int t = threadIdx.x, tx = t & 15, ty = t >> 4;
    ull acc[8][4];
    #pragma unroll
    for (int i=0;i<8;i++)
        #pragma unroll
        for (int j=0;j<4;j++) acc[i][j]=0ULL;

    const float* Ab = A + (size_t)m0*K;
    const float* Wb = W + n0;

    // per-thread load coordinates (2 rounds covering the 128x16 / 16x128 tiles)
    int arow0 = t>>2,            akc0 = (t&3)<<2;
    int arow1 = (t+256)>>2,      akc1 = ((t+256)&3)<<2;
    int brow0 = t>>5,            bnc0 = (t&31)<<2;
    int brow1 = (t+256)>>5,      bnc1 = ((t+256)&31)<<2;

    float4 avA0, avA1, avB0, avB1;

    // prologue: LDG chunk 0 -> regs -> STS buf0
    avA0 = *(const float4*)(Ab + (size_t)arow0*K + akc0);
    avA1 = *(const float4*)(Ab + (size_t)arow1*K + akc1);
    avB0 = *(const float4*)(Wb + (size_t)brow0*ldw + bnc0);
    avB1 = *(const float4*)(Wb + (size_t)brow1*ldw + bnc1);
    As[0][akc0  ][arow0]=avA0.x; As[0][akc0+1][arow0]=avA0.y;
    As[0][akc0+2][arow0]=avA0.z; As[0][akc0+3][arow0]=avA0.w;
    As[0][akc1  ][arow1]=avA1.x; As[0][akc1+1][arow1]=avA1.y;
    As[0][akc1+2][arow1]=avA1.z; As[0][akc1+3][arow1]=avA1.w;
    *(float4*)&Bs[0][brow0][bnc0] = avB0;
    *(float4*)&Bs[0][brow1][bnc1] = avB1;
    __syncthreads();

    #pragma unroll 1
    for (int c=0; c<64; c++){
        int cur = c & 1;
        if (c < 63){
            int k0 = (c+1)*16;
            avA0 = *(const float4*)(Ab + (size_t)arow0*K + k0 + akc0);
            avA1 = *(const float4*)(Ab + (size_t)arow1*K + k0 + akc1);
            avB0 = *(const float4*)(Wb + (size_t)(k0+brow0)*ldw + bnc0);
            avB1 = *(const float4*)(Wb + (size_t)(k0+brow1)*ldw + bnc1);
        }
        #pragma unroll
        for (int k=0;k<16;k++){
            float4 a0 = *(const float4*)&As[cur][k][ty*8];
            float4 a1 = *(const float4*)&As[cur][k][ty*8+4];
            float4 b0 = *(const float4*)&Bs[cur][k][tx*8];
            float4 b1 = *(const float4*)&Bs[cur][k][tx*8+4];
            ull bp[4] = {pack2(b0.x,b0.y),pack2(b0.z,b0.w),pack2(b1.x,b1.y),pack2(b1.z,b1.w)};
            float aa[8] = {a0.x,a0.y,a0.z,a0.w,a1.x,a1.y,a1.z,a1.w};
            #pragma unroll
            for (int i=0;i<8;i++){
                ull ap = pack2(aa[i], aa[i]);
                #pragma unroll
                for (int j=0;j<4;j++) acc[i][j] = fma2(ap, bp[j], acc[i][j]);
            }
        }
        if (c < 63){
            int nb = (c+1) & 1;
            As[nb][akc0  ][arow0]=avA0.x; As[nb][akc0+1][arow0]=avA0.y;
            As[nb][akc0+2][arow0]=avA0.z; As[nb][akc0+3][arow0]=avA0.w;
            As[nb][akc1  ][arow1]=avA1.x; As[nb][akc1+1][arow1]=avA1.y;
            As[nb][akc1+2][arow1]=avA1.z; As[nb][akc1+3][arow1]=avA1.w;
            *(float4*)&Bs[nb][brow0][bnc0] = avB0;
            *(float4*)&Bs[nb][brow1][bnc1] = avB1;
            __syncthreads();
        }
    }
    float bv[8];
    #pragma unroll
    for (int j=0;j<8;j++) bv[j] = bias[n0 + tx*8 + j];
    #pragma unroll
    for (int i=0;i<8;i++){
        int row = m0 + ty*8 + i;
        float o[8];
        #pragma unroll
        for (int j=0;j<4;j++){
            float2 f = unpack2(acc[i][j]);
            o[2*j]=f.x+bv[2*j]; o[2*j+1]=f.y+bv[2*j+1];
        }
        if (resid){
            const float* rp = resid + (size_t)row*CD + n0 + tx*8;
            float4 r0=*(const float4*)rp, r1=*(const float4*)(rp+4);
            o[0]+=r0.x;o[1]+=r0.y;o[2]+=r0.z;o[3]+=r0.w;
            o[4]+=r1.x;o[5]+=r1.y;o[6]+=r1.z;o[7]+=r1.w;
        }
        float* cp = C + (size_t)row*ldc + n0 + tx*8;
        *(float4*)cp     = make_float4(o[0],o[1],o[2],o[3]);
        *(float4*)(cp+4) = make_float4(o[4],o[5],o[6],o[7]);
    }
}

// ---------------- flash attention (round-1 exact) ----------------------------
#define ATTN_SMEM_FLOATS (64*132 + 64*132 + 128*68 + 128*132 + 128*17 + 3*128)
#define ATTN_SMEM_BYTES  (ATTN_SMEM_FLOATS*4)   // 180224

__global__ __launch_bounds__(256) void attn_kernel(const int* __restrict__ lens)
{
    extern __shared__ float sm[];
    float* Qs  = sm;                 // [64][132]  d-major, pre-scaled
    float* Ks  = Qs + 64*132;        // [64][132]  d-major
    float* Vs  = Ks + 64*132;        // [128][68]  k-major
    float* Ps  = Vs + 128*68;        // [128][132] q-major
    float* red = Ps + 128*132;       // [128][17]
    float* m_s = red + 128*17;       // [128]
    float* l_s = m_s + 128;          // [128]
    float* f_s = l_s + 128;          // [128]

    int qt = blockIdx.x, h = blockIdx.y, b = blockIdx.z;
    int t = threadIdx.x;
    int len = lens[b];
    int ntiles = (len + 127) >> 7;

    const float* Qg = g_qkv + (size_t)b*CS*QKV_LD + h*64;
    const float* Kg = Qg + 1024;
    const float* Vg = Qg + 2048;

    const float coef = 0.125f * 1.44269504088896341f;  // 1/sqrt(64) * log2(e)

    #pragma unroll
    for (int r=0;r<8;r++){
        int idx = t + 256*r;
        int q = idx>>4, dc = (idx&15)<<2;
        float4 v = *(const float4*)(Qg + (size_t)(qt*128+q)*QKV_LD + dc);
        Qs[(dc  )*132+q]=v.x*coef; Qs[(dc+1)*132+q]=v.y*coef;
        Qs[(dc+2)*132+q]=v.z*coef; Qs[(dc+3)*132+q]=v.w*coef;
    }
    if (t<128){ m_s[t]=NEG_INF; l_s[t]=0.f; }

    ull o2[8][4];
    #pragma unroll
    for (int i=0;i<8;i++)
        #pragma unroll
        for (int j=0;j<4;j++) o2[i][j]=0ULL;

    int txs = t & 15, tys = t >> 4;       // S-phase: 16x16 grid of 8x8 tiles
    int half = t >> 7;                     // PV k-split
    int tp = t & 127, txp = tp & 7, typ = tp >> 3;  // PV: 16(q) x 8(v) grid

    for (int kt=0; kt<ntiles; kt++){
        __syncthreads();   // prev-tile PV done before overwriting Ks/Vs
        #pragma unroll
        for (int r=0;r<8;r++){
            int idx = t + 256*r;
            int kk = idx>>4, dc = (idx&15)<<2;
            float4 v = *(const float4*)(Kg + (size_t)(kt*128+kk)*QKV_LD + dc);
            Ks[(dc  )*132+kk]=v.x; Ks[(dc+1)*132+kk]=v.y;
            Ks[(dc+2)*132+kk]=v.z; Ks[(dc+3)*132+kk]=v.w;
            float4 w = *(const float4*)(Vg + (size_t)(kt*128+kk)*QKV_LD + dc);
            *(float4*)&Vs[kk*68+dc] = w;
        }
        __syncthreads();

        // ---- S = (Q*coef) . K^T  (base-2 logits) ----
        ull s2[8][4];
        #pragma unroll
        for (int i=0;i<8;i++)
            #pragma unroll
            for (int j=0;j<4;j++) s2[i][j]=0ULL;
        #pragma unroll 4
        for (int d=0; d<64; d++){
            float4 a0 = *(const float4*)&Qs[d*132+tys*8];
            float4 a1 = *(const float4*)&Qs[d*132+tys*8+4];
            float4 b0 = *(const float4*)&Ks[d*132+txs*8];
            float4 b1 = *(const float4*)&Ks[d*132+txs*8+4];
            ull bp[4] = {pack2(b0.x,b0.y),pack2(b0.z,b0.w),pack2(b1.x,b1.y),pack2(b1.z,b1.w)};
            float aa[8] = {a0.x,a0.y,a0.z,a0.w,a1.x,a1.y,a1.z,a1.w};
            #pragma unroll
            for (int i=0;i<8;i++){
                ull ap = pack2(aa[i], aa[i]);
                #pragma unroll
                for (int j=0;j<4;j++) s2[i][j] = fma2(ap, bp[j], s2[i][j]);
            }
        }
        // unpack + key mask + per-thread row max
        float p[8][8];
        int kb = kt*128 + txs*8;
        #pragma unroll
        for (int i=0;i<8;i++){
            #pragma unroll
            for (int j=0;j<4;j++){
                float2 f = unpack2(s2[i][j]);
                p[i][2*j]=f.x; p[i][2*j+1]=f.y;
            }
            float mx = NEG_INF;
            #pragma unroll
            for (int j=0;j<8;j++){
                if (kb + j >= len) p[i][j] = NEG_INF;
                mx = fmaxf(mx, p[i][j]);
            }
            red[(tys*8+i)*17+txs] = mx;
        }
        __syncthreads();
        if (t<128){
            float mo = m_s[t];
            float mt = red[t*17];
            #pragma unroll
            for (int j=1;j<16;j++) mt = fmaxf(mt, red[t*17+j]);
            float mn = fmaxf(mo, mt);
            float f  = ex2(mo - mn);     // 0 on first tile (mo=-inf)
            m_s[t]=mn; f_s[t]=f; l_s[t]*=f;
        }
        __syncthreads();
        // ---- P = 2^(s - m), stage to SMEM, row sums ----
        #pragma unroll
        for (int i=0;i<8;i++){
            int row = tys*8+i;
            float mrow = m_s[row];
            float rs = 0.f;
            #pragma unroll
            for (int j=0;j<8;j++){ float e = ex2(p[i][j]-mrow); p[i][j]=e; rs+=e; }
            *(float4*)&Ps[row*132+txs*8]   = make_float4(p[i][0],p[i][1],p[i][2],p[i][3]);
            *(float4*)&Ps[row*132+txs*8+4] = make_float4(p[i][4],p[i][5],p[i][6],p[i][7]);
            red[row*17+txs] = rs;
        }
        __syncthreads();
        if (t<128){
            float s = red[t*17];
            #pragma unroll
            for (int j=1;j<16;j++) s += red[t*17+j];
            l_s[t] += s;
        }
        // ---- rescale O, then O += P.V over this thread's k-half ----
        #pragma unroll
        for (int i=0;i<8;i++){
            float f = f_s[typ*8+i];
            ull fp = pack2(f,f);
            #pragma unroll
            for (int j=0;j<4;j++) o2[i][j] = mul2(o2[i][j], fp);
        }
        int kbeg = half*64;
        #pragma unroll 4
        for (int k=kbeg; k<kbeg+64; k++){
            float4 v0 = *(const float4*)&Vs[k*68+txp*8];
            float4 v1 = *(const float4*)&Vs[k*68+txp*8+4];
            ull bp[4] = {pack2(v0.x,v0.y),pack2(v0.z,v0.w),pack2(v1.x,v1.y),pack2(v1.z,v1.w)};
            #pragma unroll
            for (int i=0;i<8;i++){
                float pv = Ps[(typ*8+i)*132+k];
                ull ap = pack2(pv,pv);
                #pragma unroll
                for (int j=0;j<4;j++) o2[i][j] = fma2(ap, bp[j], o2[i][j]);
            }
        }
    }
    __syncthreads();
    // merge halves through SMEM (reuse Qs region), normalize, write ctx
    float* Ob = Qs;   // 128*64 <= 64*132
    if (half==1){
        #pragma unroll
        for (int i=0;i<8;i++){
            int row = typ*8+i;
            #pragma unroll
            for (int j=0;j<4;j++){
                float2 f = unpack2(o2[i][j]);
                Ob[row*64+txp*8+2*j]   = f.x;
                Ob[row*64+txp*8+2*j+1] = f.y;
            }
        }
    }
    __syncthreads();
    if (half==0){
        #pragma unroll
        for (int i=0;i<8;i++){
            int row = typ*8+i;
            float linv = 1.0f / l_s[row];
            float o[8];
            #pragma unroll
            for (int j=0;j<4;j++){
                float2 f = unpack2(o2[i][j]);
                o[2*j]   = (f.x + Ob[row*64+txp*8+2*j])   * linv;
                o[2*j+1] = (f.y + Ob[row*64+txp*8+2*j+1]) * linv;
            }
            float* cp = g_ctx + ((size_t)b*CS + qt*128 + row)*CD + h*64 + txp*8;
            *(float4*)cp     = make_float4(o[0],o[1],o[2],o[3]);
            *(float4*)(cp+4) = make_float4(o[4],o[5],o[6],o[7]);
        }
    }
}

// ---------------- launch ------------------------------------------------------
extern "C" void kernel_launch(void* const* d_in, const int* in_sizes, int n_in,
                              void* d_out, int out_size)
{
    const float* x    = (const float*)d_in[0];
    const int*   lens = (const int*)  d_in[2];
    const float* Wq   = (const float*)d_in[3];
    const float* bq   = (const float*)d_in[4];
    const float* Wkv  = (const float*)d_in[5];
    const float* bkv  = (const float*)d_in[6];
    const float* Wo   = (const float*)d_in[7];
    const float* bo   = (const float*)d_in[8];
    const float* ga   = (const float*)d_in[9];
    const float* be   = (const float*)d_in[10];
    float* out = (float*)d_out;

    cudaFuncSetAttribute(attn_kernel, cudaFuncAttributeMaxDynamicSharedMemorySize,
                         ATTN_SMEM_BYTES);

    // 1. LayerNorm (self-attention: LN(kv)==LN(q), inputs identical)
    ln_kernel<<<NROWS, 256>>>(x, ga, be);
    // 2. Q and KV projections (double-buffered SGEMM)
    gemm_kernel<<<dim3(64, 8),  256>>>(0, Wq,  bq,  nullptr, 1024, QKV_LD);
    gemm_kernel<<<dim3(64, 16), 256>>>(1, Wkv, bkv, nullptr, 2048, QKV_LD);
    // 3. attention
    attn_kernel<<<dim3(CS/128, CH, CB), 256, ATTN_SMEM_BYTES>>>(lens);
    // 4. output projection + bias + residual
    gemm_kernel<<<dim3(64, 8), 256>>>(2, Wo, bo, out, 1024, 1024);
}

// round 12
// speedup vs baseline: 1.0933x; 1.0933x over previous
#include <cuda_runtime.h>
#include <math.h>
#include <stdint.h>

typedef unsigned long long ull;

#define CB 4
#define CS 2048
#define CD 1024
#define CH 16
#define NROWS (CB*CS)          // 8192
#define QKV_LD 3072

// ---------------- scratch (static device globals: allocation-free) ----------
__device__ float g_qnorm[(size_t)NROWS*CD];      // 32 MB
__device__ float g_qkv[(size_t)NROWS*QKV_LD];    // 96 MB : [Q(1024)|K(1024)|V(1024)]
__device__ float g_ctx[(size_t)NROWS*CD];        // 32 MB

// ---------------- f32x2 helpers (FFMA2: full-rate fp32 on sm_10x) -----------
__device__ __forceinline__ ull pack2(float x, float y){
    ull r; asm("mov.b64 %0, {%1,%2};" : "=l"(r) : "f"(x), "f"(y)); return r;
}
__device__ __forceinline__ ull fma2(ull a, ull b, ull c){
    ull d; asm("fma.rn.f32x2 %0, %1, %2, %3;" : "=l"(d) : "l"(a), "l"(b), "l"(c)); return d;
}
__device__ __forceinline__ ull mul2(ull a, ull b){
    ull d; asm("mul.rn.f32x2 %0, %1, %2;" : "=l"(d) : "l"(a), "l"(b)); return d;
}
__device__ __forceinline__ float2 unpack2(ull v){
    float2 f; asm("mov.b64 {%0,%1}, %2;" : "=f"(f.x), "=f"(f.y) : "l"(v)); return f;
}
__device__ __forceinline__ float ex2(float x){
    float r; asm("ex2.approx.ftz.f32 %0, %1;" : "=f"(r) : "f"(x)); return r;
}
#define NEG_INF (__int_as_float(0xff800000))

// ---------------- LayerNorm: one block per row (round-1 exact) ---------------
__global__ __launch_bounds__(256) void ln_kernel(
    const float* __restrict__ x, const float* __restrict__ gamma,
    const float* __restrict__ beta)
{
    __shared__ float rs[8], rss[8];
    __shared__ float mu_s, rstd_s;
    int row = blockIdx.x, t = threadIdx.x;
    float4 v = ((const float4*)(x + (size_t)row*CD))[t];
    float s  = v.x+v.y+v.z+v.w;
    float ss = v.x*v.x+v.y*v.y+v.z*v.z+v.w*v.w;
    #pragma unroll
    for (int o=16;o>0;o>>=1){ s += __shfl_xor_sync(~0u,s,o); ss += __shfl_xor_sync(~0u,ss,o); }
    if ((t&31)==0){ rs[t>>5]=s; rss[t>>5]=ss; }
    __syncthreads();
    if (t<32){
        float a  = t<8 ? rs[t]  : 0.f;
        float bq = t<8 ? rss[t] : 0.f;
        #pragma unroll
        for (int o=4;o>0;o>>=1){ a += __shfl_xor_sync(~0u,a,o); bq += __shfl_xor_sync(~0u,bq,o); }
        if (t==0){
            float mu  = a*(1.f/CD);
            float var = bq*(1.f/CD) - mu*mu;
            mu_s = mu; rstd_s = rsqrtf(var + 1e-3f);
        }
    }
    __syncthreads();
    float mu = mu_s, r = rstd_s;
    float4 g = ((const float4*)gamma)[t], bb = ((const float4*)beta)[t];
    float4 o;
    o.x=(v.x-mu)*r*g.x+bb.x; o.y=(v.y-mu)*r*g.y+bb.y;
    o.z=(v.z-mu)*r*g.z+bb.z; o.w=(v.w-mu)*r*g.w+bb.w;
    ((float4*)(g_qnorm + (size_t)row*CD))[t] = o;
}

// ---------------- 128x128x16 SGEMM, double-buffered smem ---------------------
// mode 0: C=g_qkv(+0)   A=g_qnorm  (Q proj)
// mode 1: C=g_qkv+1024  A=g_qnorm  (KV proj; rows >= len[b] skipped — masked)
// mode 2: C=outp        A=g_ctx, resid=g_qnorm (O proj)
__global__ __launch_bounds__(256) void gemm_kernel(
    int mode, const float* __restrict__ W, const float* __restrict__ bias,
    float* __restrict__ outp, int ldw, int ldc, const int* __restrict__ lens)
{
    __shared__ float As[2][16][132];
    __shared__ float Bs[2][16][128];
    const int K = CD;

    int m0 = blockIdx.x*128, n0 = blockIdx.y*128;

    // KV projection: this m-tile's rows are all key positions >= len[b] -> the
    // attention mask zeroes their contribution; skip the whole tile.
    if (mode == 1){
        int local_m = m0 & (CS-1);          // position within batch b = m0/CS
        if (local_m >= lens[m0 >> 11]) return;   // CS = 2048 = 1<<11
    }

    const float* A; float* C; const float* resid = nullptr;
    if (mode==0)      { A = g_qnorm; C = g_qkv; }
    else if (mode==1) { A = g_qnorm; C = g_qkv + 1024; }
    else              { A = g_ctx;   C = outp;  resid = g_qnorm; }

    int t = threadIdx.x, tx = t & 15, ty = t >> 4;
    ull acc[8][4];
    #pragma unroll
    for (int i=0;i<8;i++)
        #pragma unroll
        for (int j=0;j<4;j++) acc[i][j]=0ULL;

    const float* Ab = A + (size_t)m0*K;
    const float* Wb = W + n0;

    // per-thread load coordinates (2 rounds covering the 128x16 / 16x128 tiles)
    int arow0 = t>>2,            akc0 = (t&3)<<2;
    int arow1 = (t+256)>>2,      akc1 = ((t+256)&3)<<2;
    int brow0 = t>>5,            bnc0 = (t&31)<<2;
    int brow1 = (t+256)>>5,      bnc1 = ((t+256)&31)<<2;

    float4 avA0, avA1, avB0, avB1;

    // prologue: LDG chunk 0 -> regs -> STS buf0
    avA0 = *(const float4*)(Ab + (size_t)arow0*K + akc0);
    avA1 = *(const float4*)(Ab + (size_t)arow1*K + akc1);
    avB0 = *(const float4*)(Wb + (size_t)brow0*ldw + bnc0);
    avB1 = *(const float4*)(Wb + (size_t)brow1*ldw + bnc1);
    As[0][akc0  ][arow0]=avA0.x; As[0][akc0+1][arow0]=avA0.y;
    As[0][akc0+2][arow0]=avA0.z; As[0][akc0+3][arow0]=avA0.w;
    As[0][akc1  ][arow1]=avA1.x; As[0][akc1+1][arow1]=avA1.y;
    As[0][akc1+2][arow1]=avA1.z; As[0][akc1+3][arow1]=avA1.w;
    *(float4*)&Bs[0][brow0][bnc0] = avB0;
    *(float4*)&Bs[0][brow1][bnc1] = avB1;
    __syncthreads();

    #pragma unroll 1
    for (int c=0; c<64; c++){
        int cur = c & 1;
        if (c < 63){
            int k0 = (c+1)*16;
            avA0 = *(const float4*)(Ab + (size_t)arow0*K + k0 + akc0);
            avA1 = *(const float4*)(Ab + (size_t)arow1*K + k0 + akc1);
            avB0 = *(const float4*)(Wb + (size_t)(k0+brow0)*ldw + bnc0);
            avB1 = *(const float4*)(Wb + (size_t)(k0+brow1)*ldw + bnc1);
        }
        #pragma unroll
        for (int k=0;k<16;k++){
            float4 a0 = *(const float4*)&As[cur][k][ty*8];
            float4 a1 = *(const float4*)&As[cur][k][ty*8+4];
            float4 b0 = *(const float4*)&Bs[cur][k][tx*8];
            float4 b1 = *(const float4*)&Bs[cur][k][tx*8+4];
            ull bp[4] = {pack2(b0.x,b0.y),pack2(b0.z,b0.w),pack2(b1.x,b1.y),pack2(b1.z,b1.w)};
            float aa[8] = {a0.x,a0.y,a0.z,a0.w,a1.x,a1.y,a1.z,a1.w};
            #pragma unroll
            for (int i=0;i<8;i++){
                ull ap = pack2(aa[i], aa[i]);
                #pragma unroll
                for (int j=0;j<4;j++) acc[i][j] = fma2(ap, bp[j], acc[i][j]);
            }
        }
        if (c < 63){
            int nb = (c+1) & 1;
            As[nb][akc0  ][arow0]=avA0.x; As[nb][akc0+1][arow0]=avA0.y;
            As[nb][akc0+2][arow0]=avA0.z; As[nb][akc0+3][arow0]=avA0.w;
            As[nb][akc1  ][arow1]=avA1.x; As[nb][akc1+1][arow1]=avA1.y;
            As[nb][akc1+2][arow1]=avA1.z; As[nb][akc1+3][arow1]=avA1.w;
            *(float4*)&Bs[nb][brow0][bnc0] = avB0;
            *(float4*)&Bs[nb][brow1][bnc1] = avB1;
            __syncthreads();
        }
    }
    float bv[8];
    #pragma unroll
    for (int j=0;j<8;j++) bv[j] = bias[n0 + tx*8 + j];
    #pragma unroll
    for (int i=0;i<8;i++){
        int row = m0 + ty*8 + i;
        float o[8];
        #pragma unroll
        for (int j=0;j<4;j++){
            float2 f = unpack2(acc[i][j]);
            o[2*j]=f.x+bv[2*j]; o[2*j+1]=f.y+bv[2*j+1];
        }
        if (resid){
            const float* rp = resid + (size_t)row*CD + n0 + tx*8;
            float4 r0=*(const float4*)rp, r1=*(const float4*)(rp+4);
            o[0]+=r0.x;o[1]+=r0.y;o[2]+=r0.z;o[3]+=r0.w;
            o[4]+=r1.x;o[5]+=r1.y;o[6]+=r1.z;o[7]+=r1.w;
        }
        float* cp = C + (size_t)row*ldc + n0 + tx*8;
        *(float4*)cp     = make_float4(o[0],o[1],o[2],o[3]);
        *(float4*)(cp+4) = make_float4(o[4],o[5],o[6],o[7]);
    }
}

// ---------------- flash attention (round-1 exact) ----------------------------
#define ATTN_SMEM_FLOATS (64*132 + 64*132 + 128*68 + 128*132 + 128*17 + 3*128)
#define ATTN_SMEM_BYTES  (ATTN_SMEM_FLOATS*4)   // 180224

__global__ __launch_bounds__(256) void attn_kernel(const int* __restrict__ lens)
{
    extern __shared__ float sm[];
    float* Qs  = sm;                 // [64][132]  d-major, pre-scaled
    float* Ks  = Qs + 64*132;        // [64][132]  d-major
    float* Vs  = Ks + 64*132;        // [128][68]  k-major
    float* Ps  = Vs + 128*68;        // [128][132] q-major
    float* red = Ps + 128*132;       // [128][17]
    float* m_s = red + 128*17;       // [128]
    float* l_s = m_s + 128;          // [128]
    float* f_s = l_s + 128;          // [128]

    int qt = blockIdx.x, h = blockIdx.y, b = blockIdx.z;
    int t = threadIdx.x;
    int len = lens[b];
    int ntiles = (len + 127) >> 7;

    const float* Qg = g_qkv + (size_t)b*CS*QKV_LD + h*64;
    const float* Kg = Qg + 1024;
    const float* Vg = Qg + 2048;

    const float coef = 0.125f * 1.44269504088896341f;  // 1/sqrt(64) * log2(e)

    #pragma unroll
    for (int r=0;r<8;r++){
        int idx = t + 256*r;
        int q = idx>>4, dc = (idx&15)<<2;
        float4 v = *(const float4*)(Qg + (size_t)(qt*128+q)*QKV_LD + dc);
        Qs[(dc  )*132+q]=v.x*coef; Qs[(dc+1)*132+q]=v.y*coef;
        Qs[(dc+2)*132+q]=v.z*coef; Qs[(dc+3)*132+q]=v.w*coef;
    }
    if (t<128){ m_s[t]=NEG_INF; l_s[t]=0.f; }

    ull o2[8][4];
    #pragma unroll
    for (int i=0;i<8;i++)
        #pragma unroll
        for (int j=0;j<4;j++) o2[i][j]=0ULL;

    int txs = t & 15, tys = t >> 4;       // S-phase: 16x16 grid of 8x8 tiles
    int half = t >> 7;                     // PV k-split
    int tp = t & 127, txp = tp & 7, typ = tp >> 3;  // PV: 16(q) x 8(v) grid

    for (int kt=0; kt<ntiles; kt++){
        __syncthreads();   // prev-tile PV done before overwriting Ks/Vs
        #pragma unroll
        for (int r=0;r<8;r++){
            int idx = t + 256*r;
            int kk = idx>>4, dc = (idx&15)<<2;
            float4 v = *(const float4*)(Kg + (size_t)(kt*128+kk)*QKV_LD + dc);
            Ks[(dc  )*132+kk]=v.x; Ks[(dc+1)*132+kk]=v.y;
            Ks[(dc+2)*132+kk]=v.z; Ks[(dc+3)*132+kk]=v.w;
            float4 w = *(const float4*)(Vg + (size_t)(kt*128+kk)*QKV_LD + dc);
            *(float4*)&Vs[kk*68+dc] = w;
        }
        __syncthreads();

        // ---- S = (Q*coef) . K^T  (base-2 logits) ----
        ull s2[8][4];
        #pragma unroll
        for (int i=0;i<8;i++)
            #pragma unroll
            for (int j=0;j<4;j++) s2[i][j]=0ULL;
        #pragma unroll 4
        for (int d=0; d<64; d++){
            float4 a0 = *(const float4*)&Qs[d*132+tys*8];
            float4 a1 = *(const float4*)&Qs[d*132+tys*8+4];
            float4 b0 = *(const float4*)&Ks[d*132+txs*8];
            float4 b1 = *(const float4*)&Ks[d*132+txs*8+4];
            ull bp[4] = {pack2(b0.x,b0.y),pack2(b0.z,b0.w),pack2(b1.x,b1.y),pack2(b1.z,b1.w)};
            float aa[8] = {a0.x,a0.y,a0.z,a0.w,a1.x,a1.y,a1.z,a1.w};
            #pragma unroll
            for (int i=0;i<8;i++){
                ull ap = pack2(aa[i], aa[i]);
                #pragma unroll
                for (int j=0;j<4;j++) s2[i][j] = fma2(ap, bp[j], s2[i][j]);
            }
        }
        // unpack + key mask + per-thread row max
        float p[8][8];
        int kb = kt*128 + txs*8;
        #pragma unroll
        for (int i=0;i<8;i++){
            #pragma unroll
            for (int j=0;j<4;j++){
                float2 f = unpack2(s2[i][j]);
                p[i][2*j]=f.x; p[i][2*j+1]=f.y;
            }
            float mx = NEG_INF;
            #pragma unroll
            for (int j=0;j<8;j++){
                if (kb + j >= len) p[i][j] = NEG_INF;
                mx = fmaxf(mx, p[i][j]);
            }
            red[(tys*8+i)*17+txs] = mx;
        }
        __syncthreads();
        if (t<128){
            float mo = m_s[t];
            float mt = red[t*17];
            #pragma unroll
            for (int j=1;j<16;j++) mt = fmaxf(mt, red[t*17+j]);
            float mn = fmaxf(mo, mt);
            float f  = ex2(mo - mn);     // 0 on first tile (mo=-inf)
            m_s[t]=mn; f_s[t]=f; l_s[t]*=f;
        }
        __syncthreads();
        // ---- P = 2^(s - m), stage to SMEM, row sums ----
        #pragma unroll
        for (int i=0;i<8;i++){
            int row = tys*8+i;
            float mrow = m_s[row];
            float rs = 0.f;
            #pragma unroll
            for (int j=0;j<8;j++){ float e = ex2(p[i][j]-mrow); p[i][j]=e; rs+=e; }
            *(float4*)&Ps[row*132+txs*8]   = make_float4(p[i][0],p[i][1],p[i][2],p[i][3]);
            *(float4*)&Ps[row*132+txs*8+4] = make_float4(p[i][4],p[i][5],p[i][6],p[i][7]);
            red[row*17+txs] = rs;
        }
        __syncthreads();
        if (t<128){
            float s = red[t*17];
            #pragma unroll
            for (int j=1;j<16;j++) s += red[t*17+j];
            l_s[t] += s;
        }
        // ---- rescale O, then O += P.V over this thread's k-half ----
        #pragma unroll
        for (int i=0;i<8;i++){
            float f = f_s[typ*8+i];
            ull fp = pack2(f,f);
            #pragma unroll
            for (int j=0;j<4;j++) o2[i][j] = mul2(o2[i][j], fp);
        }
        int kbeg = half*64;
        #pragma unroll 4
        for (int k=kbeg; k<kbeg+64; k++){
            float4 v0 = *(const float4*)&Vs[k*68+txp*8];
            float4 v1 = *(const float4*)&Vs[k*68+txp*8+4];
            ull bp[4] = {pack2(v0.x,v0.y),pack2(v0.z,v0.w),pack2(v1.x,v1.y),pack2(v1.z,v1.w)};
            #pragma unroll
            for (int i=0;i<8;i++){
                float pv = Ps[(typ*8+i)*132+k];
                ull ap = pack2(pv,pv);
                #pragma unroll
                for (int j=0;j<4;j++) o2[i][j] = fma2(ap, bp[j], o2[i][j]);
            }
        }
    }
    __syncthreads();
    // merge halves through SMEM (reuse Qs region), normalize, write ctx
    float* Ob = Qs;   // 128*64 <= 64*132
    if (half==1){
        #pragma unroll
        for (int i=0;i<8;i++){
            int row = typ*8+i;
            #pragma unroll
            for (int j=0;j<4;j++){
                float2 f = unpack2(o2[i][j]);
                Ob[row*64+txp*8+2*j]   = f.x;
                Ob[row*64+txp*8+2*j+1] = f.y;
            }
        }
    }
    __syncthreads();
    if (half==0){
        #pragma unroll
        for (int i=0;i<8;i++){
            int row = typ*8+i;
            float linv = 1.0f / l_s[row];
            float o[8];
            #pragma unroll
            for (int j=0;j<4;j++){
                float2 f = unpack2(o2[i][j]);
                o[2*j]   = (f.x + Ob[row*64+txp*8+2*j])   * linv;
                o[2*j+1] = (f.y + Ob[row*64+txp*8+2*j+1]) * linv;
            }
            float* cp = g_ctx + ((size_t)b*CS + qt*128 + row)*CD + h*64 + txp*8;
            *(float4*)cp     = make_float4(o[0],o[1],o[2],o[3]);
            *(float4*)(cp+4) = make_float4(o[4],o[5],o[6],o[7]);
        }
    }
}

// ---------------- launch ------------------------------------------------------
extern "C" void kernel_launch(void* const* d_in, const int* in_sizes, int n_in,
                              void* d_out, int out_size)
{
    const float* x    = (const float*)d_in[0];
    const int*   lens = (const int*)  d_in[2];
    const float* Wq   = (const float*)d_in[3];
    const float* bq   = (const float*)d_in[4];
    const float* Wkv  = (const float*)d_in[5];
    const float* bkv  = (const float*)d_in[6];
    const float* Wo   = (const float*)d_in[7];
    const float* bo   = (const float*)d_in[8];
    const float* ga   = (const float*)d_in[9];
    const float* be   = (const float*)d_in[10];
    float* out = (float*)d_out;

    cudaFuncSetAttribute(attn_kernel, cudaFuncAttributeMaxDynamicSharedMemorySize,
                         ATTN_SMEM_BYTES);

    // 1. LayerNorm (self-attention: LN(kv)==LN(q), inputs identical)
    ln_kernel<<<NROWS, 256>>>(x, ga, be);
    // 2. Q and KV projections (KV skips masked key rows)
    gemm_kernel<<<dim3(64, 8),  256>>>(0, Wq,  bq,  nullptr, 1024, QKV_LD, lens);
    gemm_kernel<<<dim3(64, 16), 256>>>(1, Wkv, bkv, nullptr, 2048, QKV_LD, lens);
    // 3. attention
    attn_kernel<<<dim3(CS/128, CH, CB), 256, ATTN_SMEM_BYTES>>>(lens);
    // 4. output projection + bias + residual
    gemm_kernel<<<dim3(64, 8), 256>>>(2, Wo, bo, out, 1024, 1024, lens);
}

// round 14
// speedup vs baseline: 1.1671x; 1.0675x over previous
#include <cuda_runtime.h>
#include <math.h>
#include <stdint.h>

typedef unsigned long long ull;

#define CB 4
#define CS 2048
#define CD 1024
#define CH 16
#define NROWS (CB*CS)          // 8192
#define QKV_LD 3072

// ---------------- scratch (static device globals: allocation-free) ----------
__device__ float g_qnorm[(size_t)NROWS*CD];      // 32 MB
__device__ float g_qkv[(size_t)NROWS*QKV_LD];    // 96 MB : [Q(1024)|K(1024)|V(1024)]
__device__ float g_ctx[(size_t)NROWS*CD];        // 32 MB

// ---------------- f32x2 helpers (FFMA2: full-rate fp32 on sm_10x) -----------
__device__ __forceinline__ ull pack2(float x, float y){
    ull r; asm("mov.b64 %0, {%1,%2};" : "=l"(r) : "f"(x), "f"(y)); return r;
}
__device__ __forceinline__ ull fma2(ull a, ull b, ull c){
    ull d; asm("fma.rn.f32x2 %0, %1, %2, %3;" : "=l"(d) : "l"(a), "l"(b), "l"(c)); return d;
}
__device__ __forceinline__ ull mul2(ull a, ull b){
    ull d; asm("mul.rn.f32x2 %0, %1, %2;" : "=l"(d) : "l"(a), "l"(b)); return d;
}
__device__ __forceinline__ float2 unpack2(ull v){
    float2 f; asm("mov.b64 {%0,%1}, %2;" : "=f"(f.x), "=f"(f.y) : "l"(v)); return f;
}
__device__ __forceinline__ float ex2(float x){
    float r; asm("ex2.approx.ftz.f32 %0, %1;" : "=f"(r) : "f"(x)); return r;
}
#define NEG_INF (__int_as_float(0xff800000))

// ---------------- LayerNorm: one block per row (round-1 exact) ---------------
__global__ __launch_bounds__(256) void ln_kernel(
    const float* __restrict__ x, const float* __restrict__ gamma,
    const float* __restrict__ beta)
{
    __shared__ float rs[8], rss[8];
    __shared__ float mu_s, rstd_s;
    int row = blockIdx.x, t = threadIdx.x;
    float4 v = ((const float4*)(x + (size_t)row*CD))[t];
    float s  = v.x+v.y+v.z+v.w;
    float ss = v.x*v.x+v.y*v.y+v.z*v.z+v.w*v.w;
    #pragma unroll
    for (int o=16;o>0;o>>=1){ s += __shfl_xor_sync(~0u,s,o); ss += __shfl_xor_sync(~0u,ss,o); }
    if ((t&31)==0){ rs[t>>5]=s; rss[t>>5]=ss; }
    __syncthreads();
    if (t<32){
        float a  = t<8 ? rs[t]  : 0.f;
        float bq = t<8 ? rss[t] : 0.f;
        #pragma unroll
        for (int o=4;o>0;o>>=1){ a += __shfl_xor_sync(~0u,a,o); bq += __shfl_xor_sync(~0u,bq,o); }
        if (t==0){
            float mu  = a*(1.f/CD);
            float var = bq*(1.f/CD) - mu*mu;
            mu_s = mu; rstd_s = rsqrtf(var + 1e-3f);
        }
    }
    __syncthreads();
    float mu = mu_s, r = rstd_s;
    float4 g = ((const float4*)gamma)[t], bb = ((const float4*)beta)[t];
    float4 o;
    o.x=(v.x-mu)*r*g.x+bb.x; o.y=(v.y-mu)*r*g.y+bb.y;
    o.z=(v.z-mu)*r*g.z+bb.z; o.w=(v.w-mu)*r*g.w+bb.w;
    ((float4*)(g_qnorm + (size_t)row*CD))[t] = o;
}

// ---------------- 128x128x16 SGEMM, double-buffered smem ---------------------
// mode 0: fused QKV.  by<8 -> Q proj (W1/b1), by>=8 -> KV proj (W2/b2, masked)
// mode 2: O proj (W1/b1, resid=g_qnorm), C=outp
__global__ __launch_bounds__(256) void gemm_kernel(
    int mode, const float* __restrict__ W1, const float* __restrict__ W2,
    const float* __restrict__ b1, const float* __restrict__ b2,
    float* __restrict__ outp, const int* __restrict__ lens)
{
    __shared__ float As[2][16][132];
    __shared__ float Bs[2][16][128];
    const int K = CD;

    int m0 = blockIdx.x*128;
    const float* A; float* C; const float* residp = nullptr;
    const float* Wb; const float* biasp; int ldw, ldc;

    if (mode == 0){
        A = g_qnorm; ldc = QKV_LD;
        int by = blockIdx.y;
        if (by < 8){                       // Q projection
            int n0 = by*128;
            Wb = W1 + n0; biasp = b1 + n0; C = g_qkv + n0; ldw = 1024;
        } else {                           // KV projection (masked key rows skip)
            int local_m = m0 & (CS-1);
            if (local_m >= lens[m0 >> 11]) return;
            int n0 = (by-8)*128;
            Wb = W2 + n0; biasp = b2 + n0; C = g_qkv + 1024 + n0; ldw = 2048;
        }
    } else {
        A = g_ctx; ldc = 1024;
        int n0 = blockIdx.y*128;
        Wb = W1 + n0; biasp = b1 + n0; C = outp + n0; ldw = 1024;
        residp = g_qnorm + n0;
    }

    int t = threadIdx.x, tx = t & 15, ty = t >> 4;
    ull acc[8][4];
    #pragma unroll
    for (int i=0;i<8;i++)
        #pragma unroll
        for (int j=0;j<4;j++) acc[i][j]=0ULL;

    const float* Ab = A + (size_t)m0*K;

    int arow0 = t>>2,            akc0 = (t&3)<<2;
    int arow1 = (t+256)>>2,      akc1 = ((t+256)&3)<<2;
    int brow0 = t>>5,            bnc0 = (t&31)<<2;
    int brow1 = (t+256)>>5,      bnc1 = ((t+256)&31)<<2;

    float4 avA0, avA1, avB0, avB1;

    avA0 = *(const float4*)(Ab + (size_t)arow0*K + akc0);
    avA1 = *(const float4*)(Ab + (size_t)arow1*K + akc1);
    avB0 = *(const float4*)(Wb + (size_t)brow0*ldw + bnc0);
    avB1 = *(const float4*)(Wb + (size_t)brow1*ldw + bnc1);
    As[0][akc0  ][arow0]=avA0.x; As[0][akc0+1][arow0]=avA0.y;
    As[0][akc0+2][arow0]=avA0.z; As[0][akc0+3][arow0]=avA0.w;
    As[0][akc1  ][arow1]=avA1.x; As[0][akc1+1][arow1]=avA1.y;
    As[0][akc1+2][arow1]=avA1.z; As[0][akc1+3][arow1]=avA1.w;
    *(float4*)&Bs[0][brow0][bnc0] = avB0;
    *(float4*)&Bs[0][brow1][bnc1] = avB1;
    __syncthreads();

    #pragma unroll 1
    for (int c=0; c<64; c++){
        int cur = c & 1;
        if (c < 63){
            int k0 = (c+1)*16;
            avA0 = *(const float4*)(Ab + (size_t)arow0*K + k0 + akc0);
            avA1 = *(const float4*)(Ab + (size_t)arow1*K + k0 + akc1);
            avB0 = *(const float4*)(Wb + (size_t)(k0+brow0)*ldw + bnc0);
            avB1 = *(const float4*)(Wb + (size_t)(k0+brow1)*ldw + bnc1);
        }
        #pragma unroll
        for (int k=0;k<16;k++){
            float4 a0 = *(const float4*)&As[cur][k][ty*8];
            float4 a1 = *(const float4*)&As[cur][k][ty*8+4];
            float4 b0 = *(const float4*)&Bs[cur][k][tx*8];
            float4 b1 = *(const float4*)&Bs[cur][k][tx*8+4];
            ull bp[4] = {pack2(b0.x,b0.y),pack2(b0.z,b0.w),pack2(b1.x,b1.y),pack2(b1.z,b1.w)};
            float aa[8] = {a0.x,a0.y,a0.z,a0.w,a1.x,a1.y,a1.z,a1.w};
            #pragma unroll
            for (int i=0;i<8;i++){
                ull ap = pack2(aa[i], aa[i]);
                #pragma unroll
                for (int j=0;j<4;j++) acc[i][j] = fma2(ap, bp[j], acc[i][j]);
            }
        }
        if (c < 63){
            int nb = (c+1) & 1;
            As[nb][akc0  ][arow0]=avA0.x; As[nb][akc0+1][arow0]=avA0.y;
            As[nb][akc0+2][arow0]=avA0.z; As[nb][akc0+3][arow0]=avA0.w;
            As[nb][akc1  ][arow1]=avA1.x; As[nb][akc1+1][arow1]=avA1.y;
            As[nb][akc1+2][arow1]=avA1.z; As[nb][akc1+3][arow1]=avA1.w;
            *(float4*)&Bs[nb][brow0][bnc0] = avB0;
            *(float4*)&Bs[nb][brow1][bnc1] = avB1;
            __syncthreads();
        }
    }
    float bv[8];
    #pragma unroll
    for (int j=0;j<8;j++) bv[j] = biasp[tx*8 + j];
    #pragma unroll
    for (int i=0;i<8;i++){
        int row = m0 + ty*8 + i;
        float o[8];
        #pragma unroll
        for (int j=0;j<4;j++){
            float2 f = unpack2(acc[i][j]);
            o[2*j]=f.x+bv[2*j]; o[2*j+1]=f.y+bv[2*j+1];
        }
        if (residp){
            const float* rp = residp + (size_t)row*CD + tx*8;
            float4 r0=*(const float4*)rp, r1=*(const float4*)(rp+4);
            o[0]+=r0.x;o[1]+=r0.y;o[2]+=r0.z;o[3]+=r0.w;
            o[4]+=r1.x;o[5]+=r1.y;o[6]+=r1.z;o[7]+=r1.w;
        }
        float* cp = C + (size_t)row*ldc + tx*8;
        *(float4*)cp     = make_float4(o[0],o[1],o[2],o[3]);
        *(float4*)(cp+4) = make_float4(o[4],o[5],o[6],o[7]);
    }
}

// ---------------- flash attention (warp-remapped S-phase, deinterleaved K) ---
#define ATTN_SMEM_FLOATS (64*132 + 64*132 + 128*68 + 128*132 + 128*17 + 3*128)
#define ATTN_SMEM_BYTES  (ATTN_SMEM_FLOATS*4)   // 180224

__global__ __launch_bounds__(256) void attn_kernel(const int* __restrict__ lens)
{
    extern __shared__ float sm[];
    float* Qs  = sm;                 // [64][132]  d-major, pre-scaled
    float* Ks  = Qs + 64*132;        // [64][132]  d-major, k deinterleaved
    float* Vs  = Ks + 64*132;        // [128][68]  k-major
    float* Ps  = Vs + 128*68;        // [128][132] q-major
    float* red = Ps + 128*132;       // [128][17]
    float* m_s = red + 128*17;       // [128]
    float* l_s = m_s + 128;          // [128]
    float* f_s = l_s + 128;          // [128]

    int qt = blockIdx.x, h = blockIdx.y, b = blockIdx.z;
    int t = threadIdx.x;
    int len = lens[b];
    int ntiles = (len + 127) >> 7;

    const float* Qg = g_qkv + (size_t)b*CS*QKV_LD + h*64;
    const float* Kg = Qg + 1024;
    const float* Vg = Qg + 2048;

    const float coef = 0.125f * 1.44269504088896341f;  // 1/sqrt(64) * log2(e)

    #pragma unroll
    for (int r=0;r<8;r++){
        int idx = t + 256*r;
        int q = idx>>4, dc = (idx&15)<<2;
        float4 v = *(const float4*)(Qg + (size_t)(qt*128+q)*QKV_LD + dc);
        Qs[(dc  )*132+q]=v.x*coef; Qs[(dc+1)*132+q]=v.y*coef;
        Qs[(dc+2)*132+q]=v.z*coef; Qs[(dc+3)*132+q]=v.w*coef;
    }
    if (t<128){ m_s[t]=NEG_INF; l_s[t]=0.f; }

    ull o2[8][4];
    #pragma unroll
    for (int i=0;i<8;i++)
        #pragma unroll
        for (int j=0;j<4;j++) o2[i][j]=0ULL;

    // S-phase remap: warp covers 8 k-groups x 4 q-groups -> deduped smem lines
    int lane = t & 31, wid = t >> 5;
    int txs = (lane & 7) | ((wid & 1) << 3);      // 0..15 (k-group)
    int tys = (lane >> 3) | ((wid >> 1) << 2);    // 0..15 (q-group)
    int half = t >> 7;                     // PV k-split
    int tp = t & 127, txp = tp & 7, typ = tp >> 3;  // PV: 16(q) x 8(v) grid

    for (int kt=0; kt<ntiles; kt++){
        __syncthreads();   // prev-tile PV done before overwriting Ks/Vs
        #pragma unroll
        for (int r=0;r<8;r++){
            int idx = t + 256*r;
            int kk = idx>>4, dc = (idx&15)<<2;
            // deinterleaved physical column: k&4 selects row half, then (k>>3, k&3)
            int kkp = ((kk & 4) << 4) | ((kk >> 3) << 2) | (kk & 3);
            float4 v = *(const float4*)(Kg + (size_t)(kt*128+kk)*QKV_LD + dc);
            Ks[(dc  )*132+kkp]=v.x; Ks[(dc+1)*132+kkp]=v.y;
            Ks[(dc+2)*132+kkp]=v.z; Ks[(dc+3)*132+kkp]=v.w;
            float4 w = *(const float4*)(Vg + (size_t)(kt*128+kk)*QKV_LD + dc);
            *(float4*)&Vs[kk*68+dc] = w;
        }
        __syncthreads();

        // ---- S = (Q*coef) . K^T  (base-2 logits) ----
        ull s2[8][4];
        #pragma unroll
        for (int i=0;i<8;i++)
            #pragma unroll
            for (int j=0;j<4;j++) s2[i][j]=0ULL;
        #pragma unroll 4
        for (int d=0; d<64; d++){
            float4 a0 = *(const float4*)&Qs[d*132+tys*8];
            float4 a1 = *(const float4*)&Qs[d*132+tys*8+4];
            float4 b0 = *(const float4*)&Ks[d*132+txs*4];        // k: 8txs..8txs+3
            float4 b1 = *(const float4*)&Ks[d*132+64+txs*4];     // k: 8txs+4..8txs+7
            ull bp[4] = {pack2(b0.x,b0.y),pack2(b0.z,b0.w),pack2(b1.x,b1.y),pack2(b1.z,b1.w)};
            float aa[8] = {a0.x,a0.y,a0.z,a0.w,a1.x,a1.y,a1.z,a1.w};
            #pragma unroll
            for (int i=0;i<8;i++){
                ull ap = pack2(aa[i], aa[i]);
                #pragma unroll
                for (int j=0;j<4;j++) s2[i][j] = fma2(ap, bp[j], s2[i][j]);
            }
        }
        // unpack + key mask + per-thread row max
        float p[8][8];
        int kb = kt*128 + txs*8;
        #pragma unroll
        for (int i=0;i<8;i++){
            #pragma unroll
            for (int j=0;j<4;j++){
                float2 f = unpack2(s2[i][j]);
                p[i][2*j]=f.x; p[i][2*j+1]=f.y;
            }
            float mx = NEG_INF;
            #pragma unroll
            for (int j=0;j<8;j++){
                if (kb + j >= len) p[i][j] = NEG_INF;
                mx = fmaxf(mx, p[i][j]);
            }
            red[(tys*8+i)*17+txs] = mx;
        }
        __syncthreads();
        if (t<128){
            float mo = m_s[t];
            float mt = red[t*17];
            #pragma unroll
            for (int j=1;j<16;j++) mt = fmaxf(mt, red[t*17+j]);
            float mn = fmaxf(mo, mt);
            float f  = ex2(mo - mn);     // 0 on first tile (mo=-inf)
            m_s[t]=mn; f_s[t]=f; l_s[t]*=f;
        }
        __syncthreads();
        // ---- P = 2^(s - m), stage to SMEM, row sums ----
        #pragma unroll
        for (int i=0;i<8;i++){
            int row = tys*8+i;
            float mrow = m_s[row];
            float rs = 0.f;
            #pragma unroll
            for (int j=0;j<8;j++){ float e = ex2(p[i][j]-mrow); p[i][j]=e; rs+=e; }
            *(float4*)&Ps[row*132+txs*8]   = make_float4(p[i][0],p[i][1],p[i][2],p[i][3]);
            *(float4*)&Ps[row*132+txs*8+4] = make_float4(p[i][4],p[i][5],p[i][6],p[i][7]);
            red[row*17+txs] = rs;
        }
        __syncthreads();
        if (t<128){
            float s = red[t*17];
            #pragma unroll
            for (int j=1;j<16;j++) s += red[t*17+j];
            l_s[t] += s;
        }
        // ---- rescale O, then O += P.V over this thread's k-half ----
        #pragma unroll
        for (int i=0;i<8;i++){
            float f = f_s[typ*8+i];
            ull fp = pack2(f,f);
            #pragma unroll
            for (int j=0;j<4;j++) o2[i][j] = mul2(o2[i][j], fp);
        }
        int kbeg = half*64;
        #pragma unroll 4
        for (int k=kbeg; k<kbeg+64; k++){
            float4 v0 = *(const float4*)&Vs[k*68+txp*8];
            float4 v1 = *(const float4*)&Vs[k*68+txp*8+4];
            ull bp[4] = {pack2(v0.x,v0.y),pack2(v0.z,v0.w),pack2(v1.x,v1.y),pack2(v1.z,v1.w)};
            #pragma unroll
            for (int i=0;i<8;i++){
                float pv = Ps[(typ*8+i)*132+k];
                ull ap = pack2(pv,pv);
                #pragma unroll
                for (int j=0;j<4;j++) o2[i][j] = fma2(ap, bp[j], o2[i][j]);
            }
        }
    }
    __syncthreads();
    // merge halves through SMEM (reuse Qs region), normalize, write ctx
    float* Ob = Qs;   // 128*64 <= 64*132
    if (half==1){
        #pragma unroll
        for (int i=0;i<8;i++){
            int row = typ*8+i;
            #pragma unroll
            for (int j=0;j<4;j++){
                float2 f = unpack2(o2[i][j]);
                Ob[row*64+txp*8+2*j]   = f.x;
                Ob[row*64+txp*8+2*j+1] = f.y;
            }
        }
    }
    __syncthreads();
    if (half==0){
        #pragma unroll
        for (int i=0;i<8;i++){
            int row = typ*8+i;
            float linv = 1.0f / l_s[row];
            float o[8];
            #pragma unroll
            for (int j=0;j<4;j++){
                float2 f = unpack2(o2[i][j]);
                o[2*j]   = (f.x + Ob[row*64+txp*8+2*j])   * linv;
                o[2*j+1] = (f.y + Ob[row*64+txp*8+2*j+1]) * linv;
            }
            float* cp = g_ctx + ((size_t)b*CS + qt*128 + row)*CD + h*64 + txp*8;
            *(float4*)cp     = make_float4(o[0],o[1],o[2],o[3]);
            *(float4*)(cp+4) = make_float4(o[4],o[5],o[6],o[7]);
        }
    }
}

// ---------------- launch ------------------------------------------------------
extern "C" void kernel_launch(void* const* d_in, const int* in_sizes, int n_in,
                              void* d_out, int out_size)
{
    const float* x    = (const float*)d_in[0];
    const int*   lens = (const int*)  d_in[2];
    const float* Wq   = (const float*)d_in[3];
    const float* bq   = (const float*)d_in[4];
    const float* Wkv  = (const float*)d_in[5];
    const float* bkv  = (const float*)d_in[6];
    const float* Wo   = (const float*)d_in[7];
    const float* bo   = (const float*)d_in[8];
    const float* ga   = (const float*)d_in[9];
    const float* be   = (const float*)d_in[10];
    float* out = (float*)d_out;

    cudaFuncSetAttribute(attn_kernel, cudaFuncAttributeMaxDynamicSharedMemorySize,
                         ATTN_SMEM_BYTES);

    // 1. LayerNorm (self-attention: LN(kv)==LN(q), inputs identical)
    ln_kernel<<<NROWS, 256>>>(x, ga, be);
    // 2. fused Q + masked-KV projections (one launch, grid 64 x 24)
    gemm_kernel<<<dim3(64, 24), 256>>>(0, Wq, Wkv, bq, bkv, nullptr, lens);
    // 3. attention
    attn_kernel<<<dim3(CS/128, CH, CB), 256, ATTN_SMEM_BYTES>>>(lens);
    // 4. output projection + bias + residual
    gemm_kernel<<<dim3(64, 8), 256>>>(2, Wo, nullptr, bo, nullptr, out, lens);
}

// round 15
// speedup vs baseline: 1.2900x; 1.1053x over previous
#include <cuda_runtime.h>
#include <math.h>
#include <stdint.h>

typedef unsigned long long ull;

#define CB 4
#define CS 2048
#define CD 1024
#define CH 16
#define NROWS (CB*CS)          // 8192
#define QKV_LD 3072

// ---------------- scratch (static device globals: allocation-free) ----------
__device__ float g_qnorm[(size_t)NROWS*CD];      // 32 MB
__device__ float g_qkv[(size_t)NROWS*QKV_LD];    // 96 MB : [Q(1024)|K(1024)|V(1024)]
__device__ float g_ctx[(size_t)NROWS*CD];        // 32 MB

// ---------------- f32x2 helpers (FFMA2: full-rate fp32 on sm_10x) -----------
__device__ __forceinline__ ull pack2(float x, float y){
    ull r; asm("mov.b64 %0, {%1,%2};" : "=l"(r) : "f"(x), "f"(y)); return r;
}
__device__ __forceinline__ ull fma2(ull a, ull b, ull c){
    ull d; asm("fma.rn.f32x2 %0, %1, %2, %3;" : "=l"(d) : "l"(a), "l"(b), "l"(c)); return d;
}
__device__ __forceinline__ ull mul2(ull a, ull b){
    ull d; asm("mul.rn.f32x2 %0, %1, %2;" : "=l"(d) : "l"(a), "l"(b)); return d;
}
__device__ __forceinline__ float2 unpack2(ull v){
    float2 f; asm("mov.b64 {%0,%1}, %2;" : "=f"(f.x), "=f"(f.y) : "l"(v)); return f;
}
__device__ __forceinline__ float ex2(float x){
    float r; asm("ex2.approx.ftz.f32 %0, %1;" : "=f"(r) : "f"(x)); return r;
}
#define NEG_INF (__int_as_float(0xff800000))

// ---------------- LayerNorm: one block per row (round-1 exact) ---------------
__global__ __launch_bounds__(256) void ln_kernel(
    const float* __restrict__ x, const float* __restrict__ gamma,
    const float* __restrict__ beta)
{
    __shared__ float rs[8], rss[8];
    __shared__ float mu_s, rstd_s;
    int row = blockIdx.x, t = threadIdx.x;
    float4 v = ((const float4*)(x + (size_t)row*CD))[t];
    float s  = v.x+v.y+v.z+v.w;
    float ss = v.x*v.x+v.y*v.y+v.z*v.z+v.w*v.w;
    #pragma unroll
    for (int o=16;o>0;o>>=1){ s += __shfl_xor_sync(~0u,s,o); ss += __shfl_xor_sync(~0u,ss,o); }
    if ((t&31)==0){ rs[t>>5]=s; rss[t>>5]=ss; }
    __syncthreads();
    if (t<32){
        float a  = t<8 ? rs[t]  : 0.f;
        float bq = t<8 ? rss[t] : 0.f;
        #pragma unroll
        for (int o=4;o>0;o>>=1){ a += __shfl_xor_sync(~0u,a,o); bq += __shfl_xor_sync(~0u,bq,o); }
        if (t==0){
            float mu  = a*(1.f/CD);
            float var = bq*(1.f/CD) - mu*mu;
            mu_s = mu; rstd_s = rsqrtf(var + 1e-3f);
        }
    }
    __syncthreads();
    float mu = mu_s, r = rstd_s;
    float4 g = ((const float4*)gamma)[t], bb = ((const float4*)beta)[t];
    float4 o;
    o.x=(v.x-mu)*r*g.x+bb.x; o.y=(v.y-mu)*r*g.y+bb.y;
    o.z=(v.z-mu)*r*g.z+bb.z; o.w=(v.w-mu)*r*g.w+bb.w;
    ((float4*)(g_qnorm + (size_t)row*CD))[t] = o;
}

// ---------------- 128x128x16 SGEMM, double-buffered + deinterleaved Bs -------
// mode 0: fused QKV.  by<8 -> Q proj (W1/b1), by>=8 -> KV proj (W2/b2, masked)
// mode 2: O proj (W1/b1, resid=g_qnorm), C=outp
// Bs physical column: p(n) = ((n&4)<<4)|((n>>3)<<2)|(n&3)  (bank-spread reads)
__global__ __launch_bounds__(256) void gemm_kernel(
    int mode, const float* __restrict__ W1, const float* __restrict__ W2,
    const float* __restrict__ b1, const float* __restrict__ b2,
    float* __restrict__ outp, const int* __restrict__ lens)
{
    __shared__ float As[2][16][132];
    __shared__ float Bs[2][16][128];
    const int K = CD;

    int m0 = blockIdx.x*128;
    const float* A; float* C; const float* residp = nullptr;
    const float* Wb; const float* biasp; int ldw, ldc;

    if (mode == 0){
        A = g_qnorm; ldc = QKV_LD;
        int by = blockIdx.y;
        if (by < 8){                       // Q projection
            int n0 = by*128;
            Wb = W1 + n0; biasp = b1 + n0; C = g_qkv + n0; ldw = 1024;
        } else {                           // KV projection (masked key rows skip)
            int local_m = m0 & (CS-1);
            if (local_m >= lens[m0 >> 11]) return;
            int n0 = (by-8)*128;
            Wb = W2 + n0; biasp = b2 + n0; C = g_qkv + 1024 + n0; ldw = 2048;
        }
    } else {
        A = g_ctx; ldc = 1024;
        int n0 = blockIdx.y*128;
        Wb = W1 + n0; biasp = b1 + n0; C = outp + n0; ldw = 1024;
        residp = g_qnorm + n0;
    }

    int t = threadIdx.x, lane = t & 31, wid = t >> 5;
    // remapped compute grid: warp covers 8 n-groups x 4 m-groups
    int tx = (lane & 7) | ((wid & 1) << 3);     // 0..15 (n-group)
    int ty = (lane >> 3) | ((wid >> 1) << 2);   // 0..15 (m-group)
    ull acc[8][4];
    #pragma unroll
    for (int i=0;i<8;i++)
        #pragma unroll
        for (int j=0;j<4;j++) acc[i][j]=0ULL;

    const float* Ab = A + (size_t)m0*K;

    int arow0 = t>>2,            akc0 = (t&3)<<2;
    int arow1 = (t+256)>>2,      akc1 = ((t+256)&3)<<2;
    // Bs loader: thread quad-id q -> logical col base bn(q), phys word 4q
    int bq0  = t & 31;
    int brow0 = t>>5,            brow1 = (t+256)>>5;
    int bnc  = ((bq0 & 15) << 3) | ((bq0 >> 4) << 2);   // logical col (inverse perm)
    int bphys = bq0 << 2;                                // phys word offset

    float4 avA0, avA1, avB0, avB1;

    avA0 = *(const float4*)(Ab + (size_t)arow0*K + akc0);
    avA1 = *(const float4*)(Ab + (size_t)arow1*K + akc1);
    avB0 = *(const float4*)(Wb + (size_t)brow0*ldw + bnc);
    avB1 = *(const float4*)(Wb + (size_t)brow1*ldw + bnc);
    As[0][akc0  ][arow0]=avA0.x; As[0][akc0+1][arow0]=avA0.y;
    As[0][akc0+2][arow0]=avA0.z; As[0][akc0+3][arow0]=avA0.w;
    As[0][akc1  ][arow1]=avA1.x; As[0][akc1+1][arow1]=avA1.y;
    As[0][akc1+2][arow1]=avA1.z; As[0][akc1+3][arow1]=avA1.w;
    *(float4*)&Bs[0][brow0][bphys] = avB0;
    *(float4*)&Bs[0][brow1][bphys] = avB1;
    __syncthreads();

    #pragma unroll 1
    for (int c=0; c<64; c++){
        int cur = c & 1;
        if (c < 63){
            int k0 = (c+1)*16;
            avA0 = *(const float4*)(Ab + (size_t)arow0*K + k0 + akc0);
            avA1 = *(const float4*)(Ab + (size_t)arow1*K + k0 + akc1);
            avB0 = *(const float4*)(Wb + (size_t)(k0+brow0)*ldw + bnc);
            avB1 = *(const float4*)(Wb + (size_t)(k0+brow1)*ldw + bnc);
        }
        #pragma unroll
        for (int k=0;k<16;k++){
            float4 a0 = *(const float4*)&As[cur][k][ty*8];
            float4 a1 = *(const float4*)&As[cur][k][ty*8+4];
            float4 b0 = *(const float4*)&Bs[cur][k][tx*4];       // n: 8tx..8tx+3
            float4 b1 = *(const float4*)&Bs[cur][k][64+tx*4];    // n: 8tx+4..8tx+7
            ull bp[4] = {pack2(b0.x,b0.y),pack2(b0.z,b0.w),pack2(b1.x,b1.y),pack2(b1.z,b1.w)};
            float aa[8] = {a0.x,a0.y,a0.z,a0.w,a1.x,a1.y,a1.z,a1.w};
            #pragma unroll
            for (int i=0;i<8;i++){
                ull ap = pack2(aa[i], aa[i]);
                #pragma unroll
                for (int j=0;j<4;j++) acc[i][j] = fma2(ap, bp[j], acc[i][j]);
            }
        }
        if (c < 63){
            int nb = (c+1) & 1;
            As[nb][akc0  ][arow0]=avA0.x; As[nb][akc0+1][arow0]=avA0.y;
            As[nb][akc0+2][arow0]=avA0.z; As[nb][akc0+3][arow0]=avA0.w;
            As[nb][akc1  ][arow1]=avA1.x; As[nb][akc1+1][arow1]=avA1.y;
            As[nb][akc1+2][arow1]=avA1.z; As[nb][akc1+3][arow1]=avA1.w;
            *(float4*)&Bs[nb][brow0][bphys] = avB0;
            *(float4*)&Bs[nb][brow1][bphys] = avB1;
            __syncthreads();
        }
    }
    float bv[8];
    #pragma unroll
    for (int j=0;j<8;j++) bv[j] = biasp[tx*8 + j];
    #pragma unroll
    for (int i=0;i<8;i++){
        int row = m0 + ty*8 + i;
        float o[8];
        #pragma unroll
        for (int j=0;j<4;j++){
            float2 f = unpack2(acc[i][j]);
            o[2*j]=f.x+bv[2*j]; o[2*j+1]=f.y+bv[2*j+1];
        }
        if (residp){
            const float* rp = residp + (size_t)row*CD + tx*8;
            float4 r0=*(const float4*)rp, r1=*(const float4*)(rp+4);
            o[0]+=r0.x;o[1]+=r0.y;o[2]+=r0.z;o[3]+=r0.w;
            o[4]+=r1.x;o[5]+=r1.y;o[6]+=r1.z;o[7]+=r1.w;
        }
        float* cp = C + (size_t)row*ldc + tx*8;
        *(float4*)cp     = make_float4(o[0],o[1],o[2],o[3]);
        *(float4*)(cp+4) = make_float4(o[4],o[5],o[6],o[7]);
    }
}

// ---------------- flash attention (round-14 exact) ---------------------------
#define ATTN_SMEM_FLOATS (64*132 + 64*132 + 128*68 + 128*132 + 128*17 + 3*128)
#define ATTN_SMEM_BYTES  (ATTN_SMEM_FLOATS*4)   // 180224

__global__ __launch_bounds__(256) void attn_kernel(const int* __restrict__ lens)
{
    extern __shared__ float sm[];
    float* Qs  = sm;                 // [64][132]  d-major, pre-scaled
    float* Ks  = Qs + 64*132;        // [64][132]  d-major, k deinterleaved
    float* Vs  = Ks + 64*132;        // [128][68]  k-major
    float* Ps  = Vs + 128*68;        // [128][132] q-major
    float* red = Ps + 128*132;       // [128][17]
    float* m_s = red + 128*17;       // [128]
    float* l_s = m_s + 128;          // [128]
    float* f_s = l_s + 128;          // [128]

    int qt = blockIdx.x, h = blockIdx.y, b = blockIdx.z;
    int t = threadIdx.x;
    int len = lens[b];
    int ntiles = (len + 127) >> 7;

    const float* Qg = g_qkv + (size_t)b*CS*QKV_LD + h*64;
    const float* Kg = Qg + 1024;
    const float* Vg = Qg + 2048;

    const float coef = 0.125f * 1.44269504088896341f;  // 1/sqrt(64) * log2(e)

    #pragma unroll
    for (int r=0;r<8;r++){
        int idx = t + 256*r;
        int q = idx>>4, dc = (idx&15)<<2;
        float4 v = *(const float4*)(Qg + (size_t)(qt*128+q)*QKV_LD + dc);
        Qs[(dc  )*132+q]=v.x*coef; Qs[(dc+1)*132+q]=v.y*coef;
        Qs[(dc+2)*132+q]=v.z*coef; Qs[(dc+3)*132+q]=v.w*coef;
    }
    if (t<128){ m_s[t]=NEG_INF; l_s[t]=0.f; }

    ull o2[8][4];
    #pragma unroll
    for (int i=0;i<8;i++)
        #pragma unroll
        for (int j=0;j<4;j++) o2[i][j]=0ULL;

    int lane = t & 31, wid = t >> 5;
    int txs = (lane & 7) | ((wid & 1) << 3);      // 0..15 (k-group)
    int tys = (lane >> 3) | ((wid >> 1) << 2);    // 0..15 (q-group)
    int half = t >> 7;                     // PV k-split
    int tp = t & 127, txp = tp & 7, typ = tp >> 3;  // PV: 16(q) x 8(v) grid

    for (int kt=0; kt<ntiles; kt++){
        __syncthreads();   // prev-tile PV done before overwriting Ks/Vs
        #pragma unroll
        for (int r=0;r<8;r++){
            int idx = t + 256*r;
            int kk = idx>>4, dc = (idx&15)<<2;
            int kkp = ((kk & 4) << 4) | ((kk >> 3) << 2) | (kk & 3);
            float4 v = *(const float4*)(Kg + (size_t)(kt*128+kk)*QKV_LD + dc);
            Ks[(dc  )*132+kkp]=v.x; Ks[(dc+1)*132+kkp]=v.y;
            Ks[(dc+2)*132+kkp]=v.z; Ks[(dc+3)*132+kkp]=v.w;
            float4 w = *(const float4*)(Vg + (size_t)(kt*128+kk)*QKV_LD + dc);
            *(float4*)&Vs[kk*68+dc] = w;
        }
        __syncthreads();

        ull s2[8][4];
        #pragma unroll
        for (int i=0;i<8;i++)
            #pragma unroll
            for (int j=0;j<4;j++) s2[i][j]=0ULL;
        #pragma unroll 4
        for (int d=0; d<64; d++){
            float4 a0 = *(const float4*)&Qs[d*132+tys*8];
            float4 a1 = *(const float4*)&Qs[d*132+tys*8+4];
            float4 b0 = *(const float4*)&Ks[d*132+txs*4];        // k: 8txs..8txs+3
            float4 b1 = *(const float4*)&Ks[d*132+64+txs*4];     // k: 8txs+4..8txs+7
            ull bp[4] = {pack2(b0.x,b0.y),pack2(b0.z,b0.w),pack2(b1.x,b1.y),pack2(b1.z,b1.w)};
            float aa[8] = {a0.x,a0.y,a0.z,a0.w,a1.x,a1.y,a1.z,a1.w};
            #pragma unroll
            for (int i=0;i<8;i++){
                ull ap = pack2(aa[i], aa[i]);
                #pragma unroll
                for (int j=0;j<4;j++) s2[i][j] = fma2(ap, bp[j], s2[i][j]);
            }
        }
        float p[8][8];
        int kb = kt*128 + txs*8;
        #pragma unroll
        for (int i=0;i<8;i++){
            #pragma unroll
            for (int j=0;j<4;j++){
                float2 f = unpack2(s2[i][j]);
                p[i][2*j]=f.x; p[i][2*j+1]=f.y;
            }
            float mx = NEG_INF;
            #pragma unroll
            for (int j=0;j<8;j++){
                if (kb + j >= len) p[i][j] = NEG_INF;
                mx = fmaxf(mx, p[i][j]);
            }
            red[(tys*8+i)*17+txs] = mx;
        }
        __syncthreads();
        if (t<128){
            float mo = m_s[t];
            float mt = red[t*17];
            #pragma unroll
            for (int j=1;j<16;j++) mt = fmaxf(mt, red[t*17+j]);
            float mn = fmaxf(mo, mt);
            float f  = ex2(mo - mn);     // 0 on first tile (mo=-inf)
            m_s[t]=mn; f_s[t]=f; l_s[t]*=f;
        }
        __syncthreads();
        #pragma unroll
        for (int i=0;i<8;i++){
            int row = tys*8+i;
            float mrow = m_s[row];
            float rs = 0.f;
            #pragma unroll
            for (int j=0;j<8;j++){ float e = ex2(p[i][j]-mrow); p[i][j]=e; rs+=e; }
            *(float4*)&Ps[row*132+txs*8]   = make_float4(p[i][0],p[i][1],p[i][2],p[i][3]);
            *(float4*)&Ps[row*132+txs*8+4] = make_float4(p[i][4],p[i][5],p[i][6],p[i][7]);
            red[row*17+txs] = rs;
        }
        __syncthreads();
        if (t<128){
            float s = red[t*17];
            #pragma unroll
            for (int j=1;j<16;j++) s += red[t*17+j];
            l_s[t] += s;
        }
        #pragma unroll
        for (int i=0;i<8;i++){
            float f = f_s[typ*8+i];
            ull fp = pack2(f,f);
            #pragma unroll
            for (int j=0;j<4;j++) o2[i][j] = mul2(o2[i][j], fp);
        }
        int kbeg = half*64;
        #pragma unroll 4
        for (int k=kbeg; k<kbeg+64; k++){
            float4 v0 = *(const float4*)&Vs[k*68+txp*8];
            float4 v1 = *(const float4*)&Vs[k*68+txp*8+4];
            ull bp[4] = {pack2(v0.x,v0.y),pack2(v0.z,v0.w),pack2(v1.x,v1.y),pack2(v1.z,v1.w)};
            #pragma unroll
            for (int i=0;i<8;i++){
                float pv = Ps[(typ*8+i)*132+k];
                ull ap = pack2(pv,pv);
                #pragma unroll
                for (int j=0;j<4;j++) o2[i][j] = fma2(ap, bp[j], o2[i][j]);
            }
        }
    }
    __syncthreads();
    float* Ob = Qs;   // 128*64 <= 64*132
    if (half==1){
        #pragma unroll
        for (int i=0;i<8;i++){
            int row = typ*8+i;
            #pragma unroll
            for (int j=0;j<4;j++){
                float2 f = unpack2(o2[i][j]);
                Ob[row*64+txp*8+2*j]   = f.x;
                Ob[row*64+txp*8+2*j+1] = f.y;
            }
        }
    }
    __syncthreads();
    if (half==0){
        #pragma unroll
        for (int i=0;i<8;i++){
            int row = typ*8+i;
            float linv = 1.0f / l_s[row];
            float o[8];
            #pragma unroll
            for (int j=0;j<4;j++){
                float2 f = unpack2(o2[i][j]);
                o[2*j]   = (f.x + Ob[row*64+txp*8+2*j])   * linv;
                o[2*j+1] = (f.y + Ob[row*64+txp*8+2*j+1]) * linv;
            }
            float* cp = g_ctx + ((size_t)b*CS + qt*128 + row)*CD + h*64 + txp*8;
            *(float4*)cp     = make_float4(o[0],o[1],o[2],o[3]);
            *(float4*)(cp+4) = make_float4(o[4],o[5],o[6],o[7]);
        }
    }
}

// ---------------- launch ------------------------------------------------------
extern "C" void kernel_launch(void* const* d_in, const int* in_sizes, int n_in,
                              void* d_out, int out_size)
{
    const float* x    = (const float*)d_in[0];
    const int*   lens = (const int*)  d_in[2];
    const float* Wq   = (const float*)d_in[3];
    const float* bq   = (const float*)d_in[4];
    const float* Wkv  = (const float*)d_in[5];
    const float* bkv  = (const float*)d_in[6];
    const float* Wo   = (const float*)d_in[7];
    const float* bo   = (const float*)d_in[8];
    const float* ga   = (const float*)d_in[9];
    const float* be   = (const float*)d_in[10];
    float* out = (float*)d_out;

    cudaFuncSetAttribute(attn_kernel, cudaFuncAttributeMaxDynamicSharedMemorySize,
                         ATTN_SMEM_BYTES);

    // 1. LayerNorm (self-attention: LN(kv)==LN(q), inputs identical)
    ln_kernel<<<NROWS, 256>>>(x, ga, be);
    // 2. fused Q + masked-KV projections (one launch, grid 64 x 24)
    gemm_kernel<<<dim3(64, 24), 256>>>(0, Wq, Wkv, bq, bkv, nullptr, lens);
    // 3. attention
    attn_kernel<<<dim3(CS/128, CH, CB), 256, ATTN_SMEM_BYTES>>>(lens);
    // 4. output projection + bias + residual
    gemm_kernel<<<dim3(64, 8), 256>>>(2, Wo, nullptr, bo, nullptr, out, lens);
}

// round 17
// speedup vs baseline: 1.2951x; 1.0040x over previous
#include <cuda_runtime.h>
#include <math.h>
#include <stdint.h>

typedef unsigned long long ull;

#define CB 4
#define CS 2048
#define CD 1024
#define CH 16
#define NROWS (CB*CS)          // 8192
#define QKV_LD 3072

// ---------------- scratch (static device globals: allocation-free) ----------
__device__ float g_qnorm[(size_t)NROWS*CD];      // 32 MB
__device__ float g_qkv[(size_t)NROWS*QKV_LD];    // 96 MB : [Q(1024)|K(1024)|V(1024)]
__device__ float g_ctx[(size_t)NROWS*CD];        // 32 MB

// ---------------- f32x2 helpers (FFMA2: full-rate fp32 on sm_10x) -----------
__device__ __forceinline__ ull pack2(float x, float y){
    ull r; asm("mov.b64 %0, {%1,%2};" : "=l"(r) : "f"(x), "f"(y)); return r;
}
__device__ __forceinline__ ull fma2(ull a, ull b, ull c){
    ull d; asm("fma.rn.f32x2 %0, %1, %2, %3;" : "=l"(d) : "l"(a), "l"(b), "l"(c)); return d;
}
__device__ __forceinline__ ull mul2(ull a, ull b){
    ull d; asm("mul.rn.f32x2 %0, %1, %2;" : "=l"(d) : "l"(a), "l"(b)); return d;
}
__device__ __forceinline__ float2 unpack2(ull v){
    float2 f; asm("mov.b64 {%0,%1}, %2;" : "=f"(f.x), "=f"(f.y) : "l"(v)); return f;
}
__device__ __forceinline__ float ex2(float x){
    float r; asm("ex2.approx.ftz.f32 %0, %1;" : "=f"(r) : "f"(x)); return r;
}
#define NEG_INF (__int_as_float(0xff800000))

// ---------------- LayerNorm: one block per row (round-1 exact) ---------------
__global__ __launch_bounds__(256) void ln_kernel(
    const float* __restrict__ x, const float* __restrict__ gamma,
    const float* __restrict__ beta)
{
    __shared__ float rs[8], rss[8];
    __shared__ float mu_s, rstd_s;
    int row = blockIdx.x, t = threadIdx.x;
    float4 v = ((const float4*)(x + (size_t)row*CD))[t];
    float s  = v.x+v.y+v.z+v.w;
    float ss = v.x*v.x+v.y*v.y+v.z*v.z+v.w*v.w;
    #pragma unroll
    for (int o=16;o>0;o>>=1){ s += __shfl_xor_sync(~0u,s,o); ss += __shfl_xor_sync(~0u,ss,o); }
    if ((t&31)==0){ rs[t>>5]=s; rss[t>>5]=ss; }
    __syncthreads();
    if (t<32){
        float a  = t<8 ? rs[t]  : 0.f;
        float bq = t<8 ? rss[t] : 0.f;
        #pragma unroll
        for (int o=4;o>0;o>>=1){ a += __shfl_xor_sync(~0u,a,o); bq += __shfl_xor_sync(~0u,bq,o); }
        if (t==0){
            float mu  = a*(1.f/CD);
            float var = bq*(1.f/CD) - mu*mu;
            mu_s = mu; rstd_s = rsqrtf(var + 1e-3f);
        }
    }
    __syncthreads();
    float mu = mu_s, r = rstd_s;
    float4 g = ((const float4*)gamma)[t], bb = ((const float4*)beta)[t];
    float4 o;
    o.x=(v.x-mu)*r*g.x+bb.x; o.y=(v.y-mu)*r*g.y+bb.y;
    o.z=(v.z-mu)*r*g.z+bb.z; o.w=(v.w-mu)*r*g.w+bb.w;
    ((float4*)(g_qnorm + (size_t)row*CD))[t] = o;
}

// ---------------- 128x128x16 SGEMM, double-buffered + deinterleaved Bs -------
// mode 0: fused QKV.  by<8 -> Q proj (W1/b1), by>=8 -> KV proj (W2/b2, masked)
// mode 2: O proj (W1/b1, resid=g_qnorm), C=outp
// Bs physical column: p(n) = ((n&4)<<4)|((n>>3)<<2)|(n&3)  (bank-spread reads)
__global__ __launch_bounds__(256) void gemm_kernel(
    int mode, const float* __restrict__ W1, const float* __restrict__ W2,
    const float* __restrict__ b1, const float* __restrict__ b2,
    float* __restrict__ outp, const int* __restrict__ lens)
{
    __shared__ float As[2][16][132];
    __shared__ float Bs[2][16][128];
    const int K = CD;

    int m0 = blockIdx.x*128;
    const float* A; float* C; const float* residp = nullptr;
    const float* Wb; const float* biasp; int ldw, ldc;

    if (mode == 0){
        A = g_qnorm; ldc = QKV_LD;
        int by = blockIdx.y;
        if (by < 8){                       // Q projection
            int n0 = by*128;
            Wb = W1 + n0; biasp = b1 + n0; C = g_qkv + n0; ldw = 1024;
        } else {                           // KV projection (masked key rows skip)
            int local_m = m0 & (CS-1);
            if (local_m >= lens[m0 >> 11]) return;
            int n0 = (by-8)*128;
            Wb = W2 + n0; biasp = b2 + n0; C = g_qkv + 1024 + n0; ldw = 2048;
        }
    } else {
        A = g_ctx; ldc = 1024;
        int n0 = blockIdx.y*128;
        Wb = W1 + n0; biasp = b1 + n0; C = outp + n0; ldw = 1024;
        residp = g_qnorm + n0;
    }

    int t = threadIdx.x, lane = t & 31, wid = t >> 5;
    int tx = (lane & 7) | ((wid & 1) << 3);     // 0..15 (n-group)
    int ty = (lane >> 3) | ((wid >> 1) << 2);   // 0..15 (m-group)
    ull acc[8][4];
    #pragma unroll
    for (int i=0;i<8;i++)
        #pragma unroll
        for (int j=0;j<4;j++) acc[i][j]=0ULL;

    const float* Ab = A + (size_t)m0*K;

    int arow0 = t>>2,            akc0 = (t&3)<<2;
    int arow1 = (t+256)>>2,      akc1 = ((t+256)&3)<<2;
    int bq0  = t & 31;
    int brow0 = t>>5,            brow1 = (t+256)>>5;
    int bnc  = ((bq0 & 15) << 3) | ((bq0 >> 4) << 2);   // logical col (inverse perm)
    int bphys = bq0 << 2;                                // phys word offset

    float4 avA0, avA1, avB0, avB1;

    avA0 = *(const float4*)(Ab + (size_t)arow0*K + akc0);
    avA1 = *(const float4*)(Ab + (size_t)arow1*K + akc1);
    avB0 = *(const float4*)(Wb + (size_t)brow0*ldw + bnc);
    avB1 = *(const float4*)(Wb + (size_t)brow1*ldw + bnc);
    As[0][akc0  ][arow0]=avA0.x; As[0][akc0+1][arow0]=avA0.y;
    As[0][akc0+2][arow0]=avA0.z; As[0][akc0+3][arow0]=avA0.w;
    As[0][akc1  ][arow1]=avA1.x; As[0][akc1+1][arow1]=avA1.y;
    As[0][akc1+2][arow1]=avA1.z; As[0][akc1+3][arow1]=avA1.w;
    *(float4*)&Bs[0][brow0][bphys] = avB0;
    *(float4*)&Bs[0][brow1][bphys] = avB1;
    __syncthreads();

    #pragma unroll 1
    for (int c=0; c<64; c++){
        int cur = c & 1;
        if (c < 63){
            int k0 = (c+1)*16;
            avA0 = *(const float4*)(Ab + (size_t)arow0*K + k0 + akc0);
            avA1 = *(const float4*)(Ab + (size_t)arow1*K + k0 + akc1);
            avB0 = *(const float4*)(Wb + (size_t)(k0+brow0)*ldw + bnc);
            avB1 = *(const float4*)(Wb + (size_t)(k0+brow1)*ldw + bnc);
        }
        #pragma unroll
        for (int k=0;k<16;k++){
            float4 a0 = *(const float4*)&As[cur][k][ty*8];
            float4 a1 = *(const float4*)&As[cur][k][ty*8+4];
            float4 b0 = *(const float4*)&Bs[cur][k][tx*4];       // n: 8tx..8tx+3
            float4 b1 = *(const float4*)&Bs[cur][k][64+tx*4];    // n: 8tx+4..8tx+7
            ull bp[4] = {pack2(b0.x,b0.y),pack2(b0.z,b0.w),pack2(b1.x,b1.y),pack2(b1.z,b1.w)};
            float aa[8] = {a0.x,a0.y,a0.z,a0.w,a1.x,a1.y,a1.z,a1.w};
            #pragma unroll
            for (int i=0;i<8;i++){
                ull ap = pack2(aa[i], aa[i]);
                #pragma unroll
                for (int j=0;j<4;j++) acc[i][j] = fma2(ap, bp[j], acc[i][j]);
            }
        }
        if (c < 63){
            int nb = (c+1) & 1;
            As[nb][akc0  ][arow0]=avA0.x; As[nb][akc0+1][arow0]=avA0.y;
            As[nb][akc0+2][arow0]=avA0.z; As[nb][akc0+3][arow0]=avA0.w;
            As[nb][akc1  ][arow1]=avA1.x; As[nb][akc1+1][arow1]=avA1.y;
            As[nb][akc1+2][arow1]=avA1.z; As[nb][akc1+3][arow1]=avA1.w;
            *(float4*)&Bs[nb][brow0][bphys] = avB0;
            *(float4*)&Bs[nb][brow1][bphys] = avB1;
            __syncthreads();
        }
    }
    float bv[8];
    #pragma unroll
    for (int j=0;j<8;j++) bv[j] = biasp[tx*8 + j];
    #pragma unroll
    for (int i=0;i<8;i++){
        int row = m0 + ty*8 + i;
        float o[8];
        #pragma unroll
        for (int j=0;j<4;j++){
            float2 f = unpack2(acc[i][j]);
            o[2*j]=f.x+bv[2*j]; o[2*j+1]=f.y+bv[2*j+1];
        }
        if (residp){
            const float* rp = residp + (size_t)row*CD + tx*8;
            float4 r0=*(const float4*)rp, r1=*(const float4*)(rp+4);
            o[0]+=r0.x;o[1]+=r0.y;o[2]+=r0.z;o[3]+=r0.w;
            o[4]+=r1.x;o[5]+=r1.y;o[6]+=r1.z;o[7]+=r1.w;
        }
        float* cp = C + (size_t)row*ldc + tx*8;
        *(float4*)cp     = make_float4(o[0],o[1],o[2],o[3]);
        *(float4*)(cp+4) = make_float4(o[4],o[5],o[6],o[7]);
    }
}

// ---------------- flash attention: deinterleaved Vs + transposed P -----------
// Vs phys d-col: pv(d) = ((d&4)<<4)|((d>>3)<<2)|(d&3)  (stride 96)
// P stored transposed: Pt[r(k)][q],  r(k) = ((k&7)<<4)|(k>>3)
#define ATTN_SMEM_FLOATS (64*132 + 64*132 + 128*96 + 128*132 + 128*17 + 3*128)
#define ATTN_SMEM_BYTES  (ATTN_SMEM_FLOATS*4)   // 194560

__global__ __launch_bounds__(256) void attn_kernel(const int* __restrict__ lens)
{
    extern __shared__ float sm[];
    float* Qs  = sm;                 // [64][132]  d-major, pre-scaled
    float* Ks  = Qs + 64*132;        // [64][132]  d-major, k deinterleaved
    float* Vs  = Ks + 64*132;        // [128][96]  k-major, d deinterleaved
    float* Pt  = Vs + 128*96;        // [128][132] k-permuted rows, q-minor
    float* red = Pt + 128*132;       // [128][17]
    float* m_s = red + 128*17;       // [128]
    float* l_s = m_s + 128;          // [128]
    float* f_s = l_s + 128;          // [128]

    int qt = blockIdx.x, h = blockIdx.y, b = blockIdx.z;
    int t = threadIdx.x;
    int len = lens[b];
    int ntiles = (len + 127) >> 7;

    const float* Qg = g_qkv + (size_t)b*CS*QKV_LD + h*64;
    const float* Kg = Qg + 1024;
    const float* Vg = Qg + 2048;

    const float coef = 0.125f * 1.44269504088896341f;  // 1/sqrt(64) * log2(e)

    #pragma unroll
    for (int r=0;r<8;r++){
        int idx = t + 256*r;
        int q = idx>>4, dc = (idx&15)<<2;
        float4 v = *(const float4*)(Qg + (size_t)(qt*128+q)*QKV_LD + dc);
        Qs[(dc  )*132+q]=v.x*coef; Qs[(dc+1)*132+q]=v.y*coef;
        Qs[(dc+2)*132+q]=v.z*coef; Qs[(dc+3)*132+q]=v.w*coef;
    }
    if (t<128){ m_s[t]=NEG_INF; l_s[t]=0.f; }

    ull o2[8][4];
    #pragma unroll
    for (int i=0;i<8;i++)
        #pragma unroll
        for (int j=0;j<4;j++) o2[i][j]=0ULL;

    int lane = t & 31, wid = t >> 5;
    int txs = (lane & 7) | ((wid & 1) << 3);      // 0..15 (k-group)
    int tys = (lane >> 3) | ((wid >> 1) << 2);    // 0..15 (q-group)
    int half = t >> 7;                     // PV k-split
    int tp = t & 127, txp = tp & 7, typ = tp >> 3;  // PV: 16(q) x 8(v) grid

    for (int kt=0; kt<ntiles; kt++){
        __syncthreads();   // prev-tile PV done before overwriting Ks/Vs
        #pragma unroll
        for (int r=0;r<8;r++){
            int idx = t + 256*r;
            int kk = idx>>4, dc = (idx&15)<<2;
            int kkp = ((kk & 4) << 4) | ((kk >> 3) << 2) | (kk & 3);
            float4 v = *(const float4*)(Kg + (size_t)(kt*128+kk)*QKV_LD + dc);
            Ks[(dc  )*132+kkp]=v.x; Ks[(dc+1)*132+kkp]=v.y;
            Ks[(dc+2)*132+kkp]=v.z; Ks[(dc+3)*132+kkp]=v.w;
            float4 w = *(const float4*)(Vg + (size_t)(kt*128+kk)*QKV_LD + dc);
            int dcp = ((dc & 4) << 4) | ((dc >> 3) << 2);   // dc&3 == 0
            *(float4*)&Vs[kk*96 + dcp] = w;
        }
        __syncthreads();

        // ---- S = (Q*coef) . K^T  (base-2 logits) ----
        ull s2[8][4];
        #pragma unroll
        for (int i=0;i<8;i++)
            #pragma unroll
            for (int j=0;j<4;j++) s2[i][j]=0ULL;
        #pragma unroll 4
        for (int d=0; d<64; d++){
            float4 a0 = *(const float4*)&Qs[d*132+tys*8];
            float4 a1 = *(const float4*)&Qs[d*132+tys*8+4];
            float4 b0 = *(const float4*)&Ks[d*132+txs*4];        // k: 8txs..8txs+3
            float4 b1 = *(const float4*)&Ks[d*132+64+txs*4];     // k: 8txs+4..8txs+7
            ull bp[4] = {pack2(b0.x,b0.y),pack2(b0.z,b0.w),pack2(b1.x,b1.y),pack2(b1.z,b1.w)};
            float aa[8] = {a0.x,a0.y,a0.z,a0.w,a1.x,a1.y,a1.z,a1.w};
            #pragma unroll
            for (int i=0;i<8;i++){
                ull ap = pack2(aa[i], aa[i]);
                #pragma unroll
                for (int j=0;j<4;j++) s2[i][j] = fma2(ap, bp[j], s2[i][j]);
            }
        }
        // unpack + key mask + per-thread row max
        float p[8][8];
        int kb = kt*128 + txs*8;
        #pragma unroll
        for (int i=0;i<8;i++){
            #pragma unroll
            for (int j=0;j<4;j++){
                float2 f = unpack2(s2[i][j]);
                p[i][2*j]=f.x; p[i][2*j+1]=f.y;
            }
            float mx = NEG_INF;
            #pragma unroll
            for (int j=0;j<8;j++){
                if (kb + j >= len) p[i][j] = NEG_INF;
                mx = fmaxf(mx, p[i][j]);
            }
            red[(tys*8+i)*17+txs] = mx;
        }
        __syncthreads();
        if (t<128){
            float mo = m_s[t];
            float mt = red[t*17];
            #pragma unroll
            for (int j=1;j<16;j++) mt = fmaxf(mt, red[t*17+j]);
            float mn = fmaxf(mo, mt);
            float f  = ex2(mo - mn);     // 0 on first tile (mo=-inf)
            m_s[t]=mn; f_s[t]=f; l_s[t]*=f;
        }
        __syncthreads();
        // ---- P = 2^(s - m), row sums; store transposed into Pt ----
        #pragma unroll
        for (int i=0;i<8;i++){
            int row = tys*8+i;
            float mrow = m_s[row];
            float rs = 0.f;
            #pragma unroll
            for (int j=0;j<8;j++){ float e = ex2(p[i][j]-mrow); p[i][j]=e; rs+=e; }
            red[row*17+txs] = rs;
        }
        #pragma unroll
        for (int j=0;j<8;j++){
            int rk = (j << 4) | txs;          // r(8*txs+j)
            *(float4*)&Pt[rk*132 + tys*8]   = make_float4(p[0][j],p[1][j],p[2][j],p[3][j]);
            *(float4*)&Pt[rk*132 + tys*8+4] = make_float4(p[4][j],p[5][j],p[6][j],p[7][j]);
        }
        __syncthreads();
        if (t<128){
            float s = red[t*17];
            #pragma unroll
            for (int j=1;j<16;j++) s += red[t*17+j];
            l_s[t] += s;
        }
        // ---- rescale O, then O += P.V over this thread's k-half ----
        #pragma unroll
        for (int i=0;i<8;i++){
            float f = f_s[typ*8+i];
            ull fp = pack2(f,f);
            #pragma unroll
            for (int j=0;j<4;j++) o2[i][j] = mul2(o2[i][j], fp);
        }
        int kbeg = half*64;
        #pragma unroll 4
        for (int k=kbeg; k<kbeg+64; k++){
            float4 v0 = *(const float4*)&Vs[k*96+txp*4];         // d: 8txp..8txp+3
            float4 v1 = *(const float4*)&Vs[k*96+64+txp*4];      // d: 8txp+4..8txp+7
            ull bp[4] = {pack2(v0.x,v0.y),pack2(v0.z,v0.w),pack2(v1.x,v1.y),pack2(v1.z,v1.w)};
            int rk = ((k & 7) << 4) | (k >> 3);
            float4 pa = *(const float4*)&Pt[rk*132 + typ*8];
            float4 pb = *(const float4*)&Pt[rk*132 + typ*8+4];
            float pv[8] = {pa.x,pa.y,pa.z,pa.w,pb.x,pb.y,pb.z,pb.w};
            #pragma unroll
            for (int i=0;i<8;i++){
                ull ap = pack2(pv[i],pv[i]);
                #pragma unroll
                for (int j=0;j<4;j++) o2[i][j] = fma2(ap, bp[j], o2[i][j]);
            }
        }
    }
    __syncthreads();
    // merge halves through SMEM (reuse Qs region), normalize, write ctx
    float* Ob = Qs;   // 128*64 <= 64*132
    if (half==1){
        #pragma unroll
        for (int i=0;i<8;i++){
            int row = typ*8+i;
            #pragma unroll
            for (int j=0;j<4;j++){
                float2 f = unpack2(o2[i][j]);
                Ob[row*64+txp*8+2*j]   = f.x;
                Ob[row*64+txp*8+2*j+1] = f.y;
            }
        }
    }
    __syncthreads();
    if (half==0){
        #pragma unroll
        for (int i=0;i<8;i++){
            int row = typ*8+i;
            float linv = 1.0f / l_s[row];
            float o[8];
            #pragma unroll
            for (int j=0;j<4;j++){
                float2 f = unpack2(o2[i][j]);
                o[2*j]   = (f.x + Ob[row*64+txp*8+2*j])   * linv;
                o[2*j+1] = (f.y + Ob[row*64+txp*8+2*j+1]) * linv;
            }
            float* cp = g_ctx + ((size_t)b*CS + qt*128 + row)*CD + h*64 + txp*8;
            *(float4*)cp     = make_float4(o[0],o[1],o[2],o[3]);
            *(float4*)(cp+4) = make_float4(o[4],o[5],o[6],o[7]);
        }
    }
}

// ---------------- launch ------------------------------------------------------
extern "C" void kernel_launch(void* const* d_in, const int* in_sizes, int n_in,
                              void* d_out, int out_size)
{
    const float* x    = (const float*)d_in[0];
    const int*   lens = (const int*)  d_in[2];
    const float* Wq   = (const float*)d_in[3];
    const float* bq   = (const float*)d_in[4];
    const float* Wkv  = (const float*)d_in[5];
    const float* bkv  = (const float*)d_in[6];
    const float* Wo   = (const float*)d_in[7];
    const float* bo   = (const float*)d_in[8];
    const float* ga   = (const float*)d_in[9];
    const float* be   = (const float*)d_in[10];
    float* out = (float*)d_out;

    cudaFuncSetAttribute(attn_kernel, cudaFuncAttributeMaxDynamicSharedMemorySize,
                         ATTN_SMEM_BYTES);

    // 1. LayerNorm (self-attention: LN(kv)==LN(q), inputs identical)
    ln_kernel<<<NROWS, 256>>>(x, ga, be);
    // 2. fused Q + masked-KV projections (one launch, grid 64 x 24)
    gemm_kernel<<<dim3(64, 24), 256>>>(0, Wq, Wkv, bq, bkv, nullptr, lens);
    // 3. attention
    attn_kernel<<<dim3(CS/128, CH, CB), 256, ATTN_SMEM_BYTES>>>(lens);
    // 4. output projection + bias + residual
    gemm_kernel<<<dim3(64, 8), 256>>>(2, Wo, nullptr, bo, nullptr, out, lens);
}